// round 14
// baseline (speedup 1.0000x reference)
#include <cuda_runtime.h>
#include <cuda_bf16.h>
#include <math.h>
#include <stdint.h>

// Problem constants
#define T_   256
#define B_   128
#define F_   1024
#define U_   512
#define G4_  2048   // 4*U
#define CODES_ 1024
#define ROWS_ 32768 // T*B

#define RBLK 128    // fused persistent blocks (1/SM)
#define KC   64     // recurrence K chunk
#define HPITCH 130  // Hs row pitch (even -> aligned 8B batch pairs)

// Tensor GEMM tile: 128x128, K-chunk 64
#define BKT  64
#define APITCH 72
#define BPITCH 136
#define SA_ELEM (128 * APITCH)                  // 9216
#define SB_ELEM (BKT * BPITCH)                  // 8704
#define STAGE_ELEM (2 * SA_ELEM + 2 * SB_ELEM)  // 35840
#define GEMM_SMEM (2 * STAGE_ELEM * 2)          // 143360 B

// Fused kernel smem layout (bytes)
#define FS_WS   GEMM_SMEM                        // 143360: W_rec slice (512x16 f32)
#define FS_HS   (FS_WS + 512 * 16 * 4)           // 176128: Hs (KC x HPITCH f32)
#define FS_TILE (FS_HS + KC * HPITCH * 4)        // 209408: tile broadcast slot
#define FUSED_SMEM (FS_TILE + 16)                // 209424

// Work queue: p1 GEMM tiles | h->bf16 convert tiles | p3 GEMM tiles
#define P1_TILES (T_ * (G4_ / 128))              // 4096 (t-major: t*16+ncol)
#define CV_BASE  P1_TILES                        // 4096..4351: convert tile t
#define P3_BASE  (P1_TILES + T_)                 // 4352
#define P3_TILES (T_ * (CODES_ / 128))           // 2048 (t-major: t*8+ncol)
#define PQ_TOTAL (P3_BASE + P3_TILES)            // 6400

#define BARR1 asm volatile("bar.sync 1, 256;" ::: "memory")
#define BARR2 asm volatile("bar.sync 2, 256;" ::: "memory")

// ---------------------------------------------------------------------------
// Scratch
// ---------------------------------------------------------------------------
__device__ float g_xz   [(size_t)ROWS_ * G4_];
__device__ float g_hseq [(size_t)ROWS_ * U_];
__device__ float g_h0   [B_ * U_];
__device__ float g_Wrec4[(size_t)U_ * G4_];
__device__ float g_b4   [G4_];
__device__ unsigned g_bar;
__device__ unsigned g_q;
__device__ unsigned g_ready[T_];
__device__ unsigned g_ready3[T_];

__device__ __nv_bfloat16 g_xh [(size_t)ROWS_ * F_];
__device__ __nv_bfloat16 g_xl [(size_t)ROWS_ * F_];
__device__ __nv_bfloat16 g_Wih[(size_t)F_ * G4_];
__device__ __nv_bfloat16 g_Wil[(size_t)F_ * G4_];
__device__ __nv_bfloat16 g_Wdh[(size_t)U_ * CODES_];
__device__ __nv_bfloat16 g_Wdl[(size_t)U_ * CODES_];
__device__ __nv_bfloat16 g_hh [(size_t)ROWS_ * U_];   // UNMASKED h, hi
__device__ __nv_bfloat16 g_hl [(size_t)ROWS_ * U_];   // UNMASKED h, lo

// ---------------------------------------------------------------------------
// Helpers
// ---------------------------------------------------------------------------
__device__ __forceinline__ uint32_t smem_u32(const void* p) {
    return (uint32_t)__cvta_generic_to_shared(p);
}
__device__ __forceinline__ void cpa16(uint32_t dst, const void* src) {
    asm volatile("cp.async.cg.shared.global [%0], [%1], 16;\n" :: "r"(dst), "l"(src));
}
__device__ __forceinline__ void cpa_commit() { asm volatile("cp.async.commit_group;\n" ::); }
__device__ __forceinline__ void cpa_wait0()  { asm volatile("cp.async.wait_group 0;\n" ::); }
__device__ __forceinline__ void ldsm_x4(uint32_t& r0, uint32_t& r1, uint32_t& r2, uint32_t& r3, uint32_t a) {
    asm volatile("ldmatrix.sync.aligned.m8n8.x4.shared.b16 {%0,%1,%2,%3},[%4];"
                 : "=r"(r0), "=r"(r1), "=r"(r2), "=r"(r3) : "r"(a));
}
__device__ __forceinline__ void ldsm_x4t(uint32_t& r0, uint32_t& r1, uint32_t& r2, uint32_t& r3, uint32_t a) {
    asm volatile("ldmatrix.sync.aligned.m8n8.x4.trans.shared.b16 {%0,%1,%2,%3},[%4];"
                 : "=r"(r0), "=r"(r1), "=r"(r2), "=r"(r3) : "r"(a));
}
__device__ __forceinline__ void mma_bf16(float c[4], const uint32_t a[4], const uint32_t b[2]) {
    asm volatile(
        "mma.sync.aligned.m16n8k16.row.col.f32.bf16.bf16.f32 "
        "{%0,%1,%2,%3},{%4,%5,%6,%7},{%8,%9},{%0,%1,%2,%3};"
        : "+f"(c[0]), "+f"(c[1]), "+f"(c[2]), "+f"(c[3])
        : "r"(a[0]), "r"(a[1]), "r"(a[2]), "r"(a[3]), "r"(b[0]), "r"(b[1]));
}

// ---------------------------------------------------------------------------
// Pre-pass kernels
// ---------------------------------------------------------------------------
__global__ void reorder_gates(const float* __restrict__ W, float* __restrict__ W4, int total) {
    int idx = blockIdx.x * blockDim.x + threadIdx.x;
    if (idx >= total) return;
    int col = idx & (G4_ - 1);
    int k   = idx >> 11;
    W4[idx] = W[(size_t)k * G4_ + (col & 3) * U_ + (col >> 2)];
}

__global__ void reorder_split(const float* __restrict__ W,
                              __nv_bfloat16* __restrict__ hi,
                              __nv_bfloat16* __restrict__ lo, int total) {
    int idx = blockIdx.x * blockDim.x + threadIdx.x;
    if (idx >= total) return;
    int col = idx & (G4_ - 1);
    int k   = idx >> 11;
    float v = W[(size_t)k * G4_ + (col & 3) * U_ + (col >> 2)];
    __nv_bfloat16 h = __float2bfloat16(v);
    hi[idx] = h;
    lo[idx] = __float2bfloat16(v - __bfloat162float(h));
}

__global__ void convert_split(const float* __restrict__ src,
                              __nv_bfloat16* __restrict__ hi,
                              __nv_bfloat16* __restrict__ lo, int n4) {
    int idx = blockIdx.x * blockDim.x + threadIdx.x;
    if (idx >= n4) return;
    float4 v = *(const float4*)(src + (size_t)idx * 4);
    __nv_bfloat16 h0 = __float2bfloat16(v.x), h1 = __float2bfloat16(v.y);
    __nv_bfloat16 h2 = __float2bfloat16(v.z), h3 = __float2bfloat16(v.w);
    *(__nv_bfloat162*)(hi + (size_t)idx * 4)     = __halves2bfloat162(h0, h1);
    *(__nv_bfloat162*)(hi + (size_t)idx * 4 + 2) = __halves2bfloat162(h2, h3);
    *(__nv_bfloat162*)(lo + (size_t)idx * 4)     =
        __halves2bfloat162(__float2bfloat16(v.x - __bfloat162float(h0)),
                           __float2bfloat16(v.y - __bfloat162float(h1)));
    *(__nv_bfloat162*)(lo + (size_t)idx * 4 + 2) =
        __halves2bfloat162(__float2bfloat16(v.z - __bfloat162float(h2)),
                           __float2bfloat16(v.w - __bfloat162float(h3)));
}

__global__ void init_kernel(const float* __restrict__ b_lstm,
                            float* __restrict__ b4,
                            float* __restrict__ h0,
                            unsigned* __restrict__ bar,
                            unsigned* __restrict__ q,
                            unsigned* __restrict__ ready,
                            unsigned* __restrict__ ready3) {
    int idx = blockIdx.x * blockDim.x + threadIdx.x;
    if (idx == 0) { *bar = 0u; *q = 0u; }
    if (idx < T_) { ready[idx] = 0u; ready3[idx] = 0u; }
    if (idx < G4_) b4[idx] = b_lstm[(idx & 3) * U_ + (idx >> 2)];
    if (idx < B_ * U_) h0[idx] = 0.0f;
}

// ---------------------------------------------------------------------------
// FUSED phases 1+2+3.
// Recurrence role (threads 0-255): EXACTLY the R11 recurrence (best known).
// GEMM role (threads 256-511): queue of 6400 items:
//   [0,4096)     phase-1 GEMM tiles (t-major), publish ready[t]
//   [4096,4352)  h[t] -> bf16 hi/lo convert (gated on grid-barrier counter)
//   [4352,6400)  phase-3 GEMM tiles (gated on ready3[t]); mask applied in
//                epilogue: out = relu(mask[row]*acc + bias)  (mask commutes)
// ---------------------------------------------------------------------------
__global__ __launch_bounds__(512, 1) void fused_all(
    const __nv_bfloat16* __restrict__ Ah, const __nv_bfloat16* __restrict__ Al,
    const __nv_bfloat16* __restrict__ Bh, const __nv_bfloat16* __restrict__ Bl,
    const float* __restrict__ b4, float* xz,
    const float* __restrict__ h0, const float* __restrict__ Wrec,
    const float* __restrict__ mask,
    __nv_bfloat16* hh, __nv_bfloat16* hl,
    const __nv_bfloat16* __restrict__ Wdh, const __nv_bfloat16* __restrict__ Wdl,
    const float* __restrict__ bd, float* outp,
    float* hseq, unsigned* bar, unsigned* q,
    unsigned* ready, unsigned* ready3)
{
    extern __shared__ char smemc[];
    int tid = threadIdx.x;

    if (tid < 256) {
        // ------------------ RECURRENCE ROLE (R11 verbatim, bar 1) ---------
        float* Ws = (float*)(smemc + FS_WS);     // [512][16]
        float* Hs = (float*)(smemc + FS_HS);     // [KC][HPITCH]
        int rtid = tid;
        int blk = blockIdx.x;
        int n0 = blk * 16;
        int tx = rtid & 3;
        int ty = rtid >> 2;
        int u  = blk * 4 + tx;

        for (int l = rtid; l < 512 * 4; l += 256) {
            int row = l >> 2, c4 = l & 3;
            *(float4*)&Ws[row * 16 + c4 * 4] =
                *(const float4*)(Wrec + (size_t)row * G4_ + n0 + c4 * 4);
        }

        float creg0 = 0.0f, creg1 = 0.0f;
        const float* hp = h0;

        for (int t = 0; t < T_; t++) {
            float acc[2][4];
            #pragma unroll
            for (int i = 0; i < 2; i++)
                #pragma unroll
                for (int j = 0; j < 4; j++) acc[i][j] = 0.0f;

            for (int k0 = 0; k0 < U_; k0 += KC) {
                #pragma unroll
                for (int i = 0; i < 8; i++) {
                    int l = rtid + i * 256;
                    int b = l >> 4, k4 = l & 15;
                    float4 v = __ldcg((const float4*)(hp + (size_t)b * U_ + k0 + k4 * 4));
                    Hs[(k4 * 4 + 0) * HPITCH + b] = v.x;
                    Hs[(k4 * 4 + 1) * HPITCH + b] = v.y;
                    Hs[(k4 * 4 + 2) * HPITCH + b] = v.z;
                    Hs[(k4 * 4 + 3) * HPITCH + b] = v.w;
                }
                BARR1;

                #pragma unroll 16
                for (int kk = 0; kk < KC; kk++) {
                    float4 wv = *(float4*)&Ws[(k0 + kk) * 16 + tx * 4];
                    float2 hv = *(float2*)&Hs[kk * HPITCH + ty * 2];
                    acc[0][0] += hv.x * wv.x; acc[0][1] += hv.x * wv.y;
                    acc[0][2] += hv.x * wv.z; acc[0][3] += hv.x * wv.w;
                    acc[1][0] += hv.y * wv.x; acc[1][1] += hv.y * wv.y;
                    acc[1][2] += hv.y * wv.z; acc[1][3] += hv.y * wv.w;
                }
                BARR1;
            }

            if (rtid == 0) {
                while (((volatile unsigned*)ready)[t] < 16u) {}
                __threadfence();
            }
            BARR1;

            #pragma unroll
            for (int i = 0; i < 2; i++) {
                int b = ty * 2 + i;
                const float4* xzp = (const float4*)(xz + ((size_t)t * B_ + b) * G4_ + n0 + tx * 4);
                float4 xv = __ldcg(xzp);
                float zi = acc[i][0] + xv.x;
                float zf = acc[i][1] + xv.y;
                float zg = acc[i][2] + xv.z;
                float zo = acc[i][3] + xv.w;
                float ig = 1.0f / (1.0f + expf(-zi));
                float fg = 1.0f / (1.0f + expf(-zf));
                float gg = tanhf(zg);
                float og = 1.0f / (1.0f + expf(-zo));
                float cp = i ? creg1 : creg0;
                float cn = fg * cp + ig * gg;
                if (i) creg1 = cn; else creg0 = cn;
                hseq[((size_t)t * B_ + b) * U_ + u] = og * tanhf(cn);
            }

            __threadfence();
            BARR1;
            if (rtid == 0) {
                atomicAdd(bar, 1u);
                unsigned target = (unsigned)RBLK * (unsigned)(t + 1);
                while (*(volatile unsigned*)bar < target) {}
            }
            BARR1;

            hp = hseq + (size_t)t * B_ * U_;
        }
    } else {
        // ------------------ WORKER ROLE (bar 2) ---------------------------
        __nv_bfloat16* ts = (__nv_bfloat16*)smemc;
        volatile int* sm_tile = (volatile int*)(smemc + FS_TILE);
        int wtid = tid - 256;
        int warp = wtid >> 5, lane = wtid & 31;
        int wm = warp >> 1, wn = warp & 1;

        int a_r = (lane & 15);
        int a_c = (lane >> 4) * 8;
        int aoffA = (wm * 32 + a_r) * APITCH + a_c;
        int aoffB = a_r * BPITCH + wn * 64 + a_c;

        for (;;) {
            if (wtid == 0) *sm_tile = (int)atomicAdd(q, 1u);
            BARR2;
            int tile = *sm_tile;
            BARR2;
            if (tile >= PQ_TOTAL) break;

            // ---- convert tile: h[t] -> unmasked bf16 hi/lo ----
            if (tile >= CV_BASE && tile < P3_BASE) {
                int tt = tile - CV_BASE;
                if (wtid == 0) {
                    unsigned tgt = (unsigned)RBLK * (unsigned)(tt + 1);
                    while (*(volatile unsigned*)bar < tgt) {}
                    __threadfence();
                }
                BARR2;
                size_t base = (size_t)tt * B_ * U_;
                const float4* src = (const float4*)(hseq + base);
                #pragma unroll 4
                for (int j = 0; j < 64; j++) {
                    int idx = wtid + j * 256;            // 0..16383 float4
                    float4 v = __ldcg(src + idx);
                    __nv_bfloat16 h0b = __float2bfloat16(v.x), h1b = __float2bfloat16(v.y);
                    __nv_bfloat16 h2b = __float2bfloat16(v.z), h3b = __float2bfloat16(v.w);
                    size_t e = base + (size_t)idx * 4;
                    *(__nv_bfloat162*)(hh + e)     = __halves2bfloat162(h0b, h1b);
                    *(__nv_bfloat162*)(hh + e + 2) = __halves2bfloat162(h2b, h3b);
                    *(__nv_bfloat162*)(hl + e)     =
                        __halves2bfloat162(__float2bfloat16(v.x - __bfloat162float(h0b)),
                                           __float2bfloat16(v.y - __bfloat162float(h1b)));
                    *(__nv_bfloat162*)(hl + e + 2) =
                        __halves2bfloat162(__float2bfloat16(v.z - __bfloat162float(h2b)),
                                           __float2bfloat16(v.w - __bfloat162float(h3b)));
                }
                __threadfence();
                BARR2;
                if (wtid == 0) atomicAdd(ready3 + tt, 1u);
                continue;
            }

            // ---- GEMM tile (phase 1 or phase 3) ----
            const __nv_bfloat16 *pAh, *pAl, *pBh, *pBl;
            const float* pbias;
            float* pC;
            int Kg, Ng, KTl, m0, n0, isP3;

            if (tile < P1_TILES) {
                m0 = (tile >> 4) * 128;
                n0 = (tile & 15) * 128;
                pAh = Ah; pAl = Al; pBh = Bh; pBl = Bl;
                pbias = b4; pC = xz;
                Kg = F_; Ng = G4_; KTl = F_ / BKT; isP3 = 0;
            } else {
                int p3 = tile - P3_BASE;
                int tt = p3 >> 3;
                m0 = tt * 128;
                n0 = (p3 & 7) * 128;
                pAh = hh; pAl = hl; pBh = Wdh; pBl = Wdl;
                pbias = bd; pC = outp;
                Kg = U_; Ng = CODES_; KTl = U_ / BKT; isP3 = 1;
                if (wtid == 0) {
                    while (((volatile unsigned*)ready3)[tt] == 0u) {}
                    __threadfence();
                }
                BARR2;
            }

            float acc[2][8][4];
            #pragma unroll
            for (int i = 0; i < 2; i++)
                #pragma unroll
                for (int j = 0; j < 8; j++)
                    #pragma unroll
                    for (int qq = 0; qq < 4; qq++) acc[i][j][qq] = 0.0f;

            auto load_stage = [&](int kt, int s) {
                __nv_bfloat16* st = ts + s * STAGE_ELEM;
                __nv_bfloat16* sAh = st;
                __nv_bfloat16* sAl = st + SA_ELEM;
                __nv_bfloat16* sBh = st + 2 * SA_ELEM;
                __nv_bfloat16* sBl = st + 2 * SA_ELEM + SB_ELEM;
                int k0 = kt * BKT;
                const __nv_bfloat16* gAh = pAh + (size_t)m0 * Kg + k0;
                const __nv_bfloat16* gAl = pAl + (size_t)m0 * Kg + k0;
                const __nv_bfloat16* gBh = pBh + (size_t)k0 * Ng + n0;
                const __nv_bfloat16* gBl = pBl + (size_t)k0 * Ng + n0;
                #pragma unroll
                for (int j = 0; j < 4; j++) {
                    int ca = wtid + j * 256;
                    int ar = ca >> 3, as = ca & 7;
                    cpa16(smem_u32(sAh + ar * APITCH + as * 8), gAh + (size_t)ar * Kg + as * 8);
                    cpa16(smem_u32(sAl + ar * APITCH + as * 8), gAl + (size_t)ar * Kg + as * 8);
                    int br = ca >> 4, bs = ca & 15;
                    cpa16(smem_u32(sBh + br * BPITCH + bs * 8), gBh + (size_t)br * Ng + bs * 8);
                    cpa16(smem_u32(sBl + br * BPITCH + bs * 8), gBl + (size_t)br * Ng + bs * 8);
                }
            };

            load_stage(0, 0);
            cpa_commit();
            cpa_wait0();
            BARR2;

            for (int kt = 0; kt < KTl; kt++) {
                int cur = kt & 1;
                if (kt + 1 < KTl) {
                    load_stage(kt + 1, cur ^ 1);
                    cpa_commit();
                }

                __nv_bfloat16* st = ts + cur * STAGE_ELEM;
                uint32_t aAh = smem_u32(st + aoffA);
                uint32_t aAl = smem_u32(st + SA_ELEM + aoffA);
                uint32_t aBh = smem_u32(st + 2 * SA_ELEM + aoffB);
                uint32_t aBl = smem_u32(st + 2 * SA_ELEM + SB_ELEM + aoffB);

                #pragma unroll
                for (int kk = 0; kk < 4; kk++) {
                    uint32_t Ahf[2][4], Alf[2][4];
                    #pragma unroll
                    for (int mt = 0; mt < 2; mt++) {
                        uint32_t off = (mt * 16) * APITCH * 2 + kk * 16 * 2;
                        ldsm_x4(Ahf[mt][0], Ahf[mt][1], Ahf[mt][2], Ahf[mt][3], aAh + off);
                        ldsm_x4(Alf[mt][0], Alf[mt][1], Alf[mt][2], Alf[mt][3], aAl + off);
                    }
                    uint32_t Bhf[8][2], Blf[8][2];
                    #pragma unroll
                    for (int p = 0; p < 4; p++) {
                        uint32_t off = (kk * 16) * BPITCH * 2 + p * 16 * 2;
                        ldsm_x4t(Bhf[2*p][0], Bhf[2*p][1], Bhf[2*p+1][0], Bhf[2*p+1][1], aBh + off);
                        ldsm_x4t(Blf[2*p][0], Blf[2*p][1], Blf[2*p+1][0], Blf[2*p+1][1], aBl + off);
                    }
                    #pragma unroll
                    for (int mt = 0; mt < 2; mt++)
                        #pragma unroll
                        for (int nt = 0; nt < 8; nt++) {
                            mma_bf16(acc[mt][nt], Ahf[mt], Bhf[nt]);
                            mma_bf16(acc[mt][nt], Ahf[mt], Blf[nt]);
                            mma_bf16(acc[mt][nt], Alf[mt], Bhf[nt]);
                        }
                }

                if (kt + 1 < KTl) cpa_wait0();
                BARR2;
            }

            int crow = lane >> 2;
            int ccol = (lane & 3) * 2;
            #pragma unroll
            for (int mt = 0; mt < 2; mt++) {
                int r0 = m0 + wm * 32 + mt * 16 + crow;
                float ms0 = 1.0f, ms1 = 1.0f;
                if (isP3) { ms0 = __ldg(mask + r0); ms1 = __ldg(mask + r0 + 8); }
                #pragma unroll
                for (int nt = 0; nt < 8; nt++) {
                    int cglob = n0 + wn * 64 + nt * 8 + ccol;
                    float b0 = pbias[cglob], b1 = pbias[cglob + 1];
                    float2 v0, v1;
                    if (isP3) {
                        v0.x = fmaxf(acc[mt][nt][0] * ms0 + b0, 0.f);
                        v0.y = fmaxf(acc[mt][nt][1] * ms0 + b1, 0.f);
                        v1.x = fmaxf(acc[mt][nt][2] * ms1 + b0, 0.f);
                        v1.y = fmaxf(acc[mt][nt][3] * ms1 + b1, 0.f);
                    } else {
                        v0.x = acc[mt][nt][0] + b0;
                        v0.y = acc[mt][nt][1] + b1;
                        v1.x = acc[mt][nt][2] + b0;
                        v1.y = acc[mt][nt][3] + b1;
                    }
                    *(float2*)(pC + (size_t)r0 * Ng + cglob)       = v0;
                    *(float2*)(pC + (size_t)(r0 + 8) * Ng + cglob) = v1;
                }
            }

            if (!isP3) {
                __threadfence();
                BARR2;
                if (wtid == 0) atomicAdd(ready + (m0 >> 7), 1u);
            }
        }
    }
}

// ---------------------------------------------------------------------------
// In-place row softmax (1024 cols, one block/row).
// ---------------------------------------------------------------------------
__global__ __launch_bounds__(256) void softmax_kernel(float* __restrict__ out) {
    __shared__ float red[8];
    int tid = threadIdx.x;
    float* p = out + (size_t)blockIdx.x * CODES_;

    float4 v = *(float4*)(p + tid * 4);
    float m = fmaxf(fmaxf(v.x, v.y), fmaxf(v.z, v.w));
    #pragma unroll
    for (int o = 16; o > 0; o >>= 1) m = fmaxf(m, __shfl_xor_sync(0xFFFFFFFFu, m, o));
    if ((tid & 31) == 0) red[tid >> 5] = m;
    __syncthreads();
    float bm = red[0];
    #pragma unroll
    for (int i = 1; i < 8; i++) bm = fmaxf(bm, red[i]);
    __syncthreads();

    v.x = expf(v.x - bm); v.y = expf(v.y - bm);
    v.z = expf(v.z - bm); v.w = expf(v.w - bm);
    float s = v.x + v.y + v.z + v.w;
    #pragma unroll
    for (int o = 16; o > 0; o >>= 1) s += __shfl_xor_sync(0xFFFFFFFFu, s, o);
    if ((tid & 31) == 0) red[tid >> 5] = s;
    __syncthreads();
    float bs = red[0];
    #pragma unroll
    for (int i = 1; i < 8; i++) bs += red[i];
    float inv = 1.0f / bs;
    v.x *= inv; v.y *= inv; v.z *= inv; v.w *= inv;
    *(float4*)(p + tid * 4) = v;
}

// ---------------------------------------------------------------------------
// Launch
// ---------------------------------------------------------------------------
extern "C" void kernel_launch(void* const* d_in, const int* in_sizes, int n_in,
                              void* d_out, int out_size) {
    const float* x       = (const float*)d_in[0];
    const float* mask    = (const float*)d_in[1];
    const float* W_in    = (const float*)d_in[2];
    const float* W_rec   = (const float*)d_in[3];
    const float* b_lstm  = (const float*)d_in[4];
    const float* W_dense = (const float*)d_in[5];
    const float* b_dense = (const float*)d_in[6];
    float* out = (float*)d_out;

    float *xz, *hseq, *h0, *Wrec4, *b4;
    unsigned *bar, *q, *ready, *ready3;
    __nv_bfloat16 *xh, *xl, *Wih, *Wil, *Wdh, *Wdl, *hh, *hl;
    cudaGetSymbolAddress((void**)&xz,     g_xz);
    cudaGetSymbolAddress((void**)&hseq,   g_hseq);
    cudaGetSymbolAddress((void**)&h0,     g_h0);
    cudaGetSymbolAddress((void**)&Wrec4,  g_Wrec4);
    cudaGetSymbolAddress((void**)&b4,     g_b4);
    cudaGetSymbolAddress((void**)&bar,    g_bar);
    cudaGetSymbolAddress((void**)&q,      g_q);
    cudaGetSymbolAddress((void**)&ready,  g_ready);
    cudaGetSymbolAddress((void**)&ready3, g_ready3);
    cudaGetSymbolAddress((void**)&xh,     g_xh);
    cudaGetSymbolAddress((void**)&xl,     g_xl);
    cudaGetSymbolAddress((void**)&Wih,    g_Wih);
    cudaGetSymbolAddress((void**)&Wil,    g_Wil);
    cudaGetSymbolAddress((void**)&Wdh,    g_Wdh);
    cudaGetSymbolAddress((void**)&Wdl,    g_Wdl);
    cudaGetSymbolAddress((void**)&hh,     g_hh);
    cudaGetSymbolAddress((void**)&hl,     g_hl);

    cudaFuncSetAttribute(fused_all,
                         cudaFuncAttributeMaxDynamicSharedMemorySize, FUSED_SMEM);

    // Pre-passes
    reorder_gates<<<(U_ * G4_ + 255) / 256, 256>>>(W_rec, Wrec4, U_ * G4_);
    reorder_split<<<(F_ * G4_ + 255) / 256, 256>>>(W_in, Wih, Wil, F_ * G4_);
    convert_split<<<(U_ * CODES_ / 4 + 255) / 256, 256>>>(W_dense, Wdh, Wdl, U_ * CODES_ / 4);
    convert_split<<<((int)((size_t)ROWS_ * F_ / 4) + 255) / 256, 256>>>(x, xh, xl, (int)((size_t)ROWS_ * F_ / 4));
    init_kernel<<<(B_ * U_ + 255) / 256, 256>>>(b_lstm, b4, h0, bar, q, ready, ready3);

    // Phases 1+2+3 fused
    fused_all<<<RBLK, 512, FUSED_SMEM>>>(
        xh, xl, Wih, Wil, b4, xz, h0, Wrec4,
        mask, hh, hl, Wdh, Wdl, b_dense, out,
        hseq, bar, q, ready, ready3);

    // Phase 4: softmax
    softmax_kernel<<<ROWS_, 256>>>(out);
}

// round 15
// speedup vs baseline: 1.2554x; 1.2554x over previous
#include <cuda_runtime.h>
#include <cuda_bf16.h>
#include <math.h>
#include <stdint.h>

// Problem constants
#define T_   256
#define B_   128
#define F_   1024
#define U_   512
#define G4_  2048   // 4*U
#define CODES_ 1024
#define ROWS_ 32768 // T*B

#define RBLK 128    // fused persistent blocks (1/SM)
#define KC   64     // recurrence K chunk
#define HP2  68     // Hs row pitch, batch-major [b][kk] (mult of 4 -> STS.128)

// Tensor GEMM tile: 128x128, K-chunk 64
#define BKT  64
#define APITCH 72
#define BPITCH 136
#define SA_ELEM (128 * APITCH)                  // 9216
#define SB_ELEM (BKT * BPITCH)                  // 8704
#define STAGE_ELEM (2 * SA_ELEM + 2 * SB_ELEM)  // 35840
#define GEMM_SMEM (2 * STAGE_ELEM * 2)          // 143360 B

// Fused kernel smem layout (bytes)
#define FS_WS   GEMM_SMEM                        // 143360: W_rec slice (512x16 f32)
#define FS_HS   (FS_WS + 512 * 16 * 4)           // 176128: Hs (B_ x HP2 f32)
#define FS_TILE (FS_HS + B_ * HP2 * 4)           // 210944: tile broadcast slot
#define FUSED_SMEM (FS_TILE + 16)                // 210960

#define P1_TILES (T_ * (G4_ / 128))              // 4096 tiles, 16 per timestep

#define BARR1 asm volatile("bar.sync 1, 256;" ::: "memory")
#define BARR2 asm volatile("bar.sync 2, 256;" ::: "memory")

// ---------------------------------------------------------------------------
// Scratch
// ---------------------------------------------------------------------------
__device__ float g_xz   [(size_t)ROWS_ * G4_];
__device__ float g_hseq [(size_t)ROWS_ * U_];
__device__ float g_h0   [B_ * U_];
__device__ float g_Wrec4[(size_t)U_ * G4_];
__device__ float g_b4   [G4_];
__device__ unsigned g_bar;
__device__ unsigned g_q;
__device__ unsigned g_ready[T_];

__device__ __nv_bfloat16 g_xh [(size_t)ROWS_ * F_];
__device__ __nv_bfloat16 g_xl [(size_t)ROWS_ * F_];
__device__ __nv_bfloat16 g_Wih[(size_t)F_ * G4_];
__device__ __nv_bfloat16 g_Wil[(size_t)F_ * G4_];
__device__ __nv_bfloat16 g_Wdh[(size_t)U_ * CODES_];
__device__ __nv_bfloat16 g_Wdl[(size_t)U_ * CODES_];
__device__ __nv_bfloat16 g_hh [(size_t)ROWS_ * U_];
__device__ __nv_bfloat16 g_hl [(size_t)ROWS_ * U_];

// ---------------------------------------------------------------------------
// Helpers
// ---------------------------------------------------------------------------
__device__ __forceinline__ uint32_t smem_u32(const void* p) {
    return (uint32_t)__cvta_generic_to_shared(p);
}
__device__ __forceinline__ void cpa16(uint32_t dst, const void* src) {
    asm volatile("cp.async.cg.shared.global [%0], [%1], 16;\n" :: "r"(dst), "l"(src));
}
__device__ __forceinline__ void cpa_commit() { asm volatile("cp.async.commit_group;\n" ::); }
__device__ __forceinline__ void cpa_wait0()  { asm volatile("cp.async.wait_group 0;\n" ::); }
__device__ __forceinline__ void ldsm_x4(uint32_t& r0, uint32_t& r1, uint32_t& r2, uint32_t& r3, uint32_t a) {
    asm volatile("ldmatrix.sync.aligned.m8n8.x4.shared.b16 {%0,%1,%2,%3},[%4];"
                 : "=r"(r0), "=r"(r1), "=r"(r2), "=r"(r3) : "r"(a));
}
__device__ __forceinline__ void ldsm_x4t(uint32_t& r0, uint32_t& r1, uint32_t& r2, uint32_t& r3, uint32_t a) {
    asm volatile("ldmatrix.sync.aligned.m8n8.x4.trans.shared.b16 {%0,%1,%2,%3},[%4];"
                 : "=r"(r0), "=r"(r1), "=r"(r2), "=r"(r3) : "r"(a));
}
__device__ __forceinline__ void mma_bf16(float c[4], const uint32_t a[4], const uint32_t b[2]) {
    asm volatile(
        "mma.sync.aligned.m16n8k16.row.col.f32.bf16.bf16.f32 "
        "{%0,%1,%2,%3},{%4,%5,%6,%7},{%8,%9},{%0,%1,%2,%3};"
        : "+f"(c[0]), "+f"(c[1]), "+f"(c[2]), "+f"(c[3])
        : "r"(a[0]), "r"(a[1]), "r"(a[2]), "r"(a[3]), "r"(b[0]), "r"(b[1]));
}

// ---------------------------------------------------------------------------
// Pre-pass kernels
// ---------------------------------------------------------------------------
__global__ void reorder_gates(const float* __restrict__ W, float* __restrict__ W4, int total) {
    int idx = blockIdx.x * blockDim.x + threadIdx.x;
    if (idx >= total) return;
    int col = idx & (G4_ - 1);
    int k   = idx >> 11;
    W4[idx] = W[(size_t)k * G4_ + (col & 3) * U_ + (col >> 2)];
}

__global__ void reorder_split(const float* __restrict__ W,
                              __nv_bfloat16* __restrict__ hi,
                              __nv_bfloat16* __restrict__ lo, int total) {
    int idx = blockIdx.x * blockDim.x + threadIdx.x;
    if (idx >= total) return;
    int col = idx & (G4_ - 1);
    int k   = idx >> 11;
    float v = W[(size_t)k * G4_ + (col & 3) * U_ + (col >> 2)];
    __nv_bfloat16 h = __float2bfloat16(v);
    hi[idx] = h;
    lo[idx] = __float2bfloat16(v - __bfloat162float(h));
}

__global__ void convert_split(const float* __restrict__ src,
                              __nv_bfloat16* __restrict__ hi,
                              __nv_bfloat16* __restrict__ lo, int n4) {
    int idx = blockIdx.x * blockDim.x + threadIdx.x;
    if (idx >= n4) return;
    float4 v = *(const float4*)(src + (size_t)idx * 4);
    __nv_bfloat16 h0 = __float2bfloat16(v.x), h1 = __float2bfloat16(v.y);
    __nv_bfloat16 h2 = __float2bfloat16(v.z), h3 = __float2bfloat16(v.w);
    *(__nv_bfloat162*)(hi + (size_t)idx * 4)     = __halves2bfloat162(h0, h1);
    *(__nv_bfloat162*)(hi + (size_t)idx * 4 + 2) = __halves2bfloat162(h2, h3);
    *(__nv_bfloat162*)(lo + (size_t)idx * 4)     =
        __halves2bfloat162(__float2bfloat16(v.x - __bfloat162float(h0)),
                           __float2bfloat16(v.y - __bfloat162float(h1)));
    *(__nv_bfloat162*)(lo + (size_t)idx * 4 + 2) =
        __halves2bfloat162(__float2bfloat16(v.z - __bfloat162float(h2)),
                           __float2bfloat16(v.w - __bfloat162float(h3)));
}

__global__ void convert_mask(const float* __restrict__ hseq,
                             const float* __restrict__ mask,
                             __nv_bfloat16* __restrict__ hi,
                             __nv_bfloat16* __restrict__ lo, int n4) {
    int idx = blockIdx.x * blockDim.x + threadIdx.x;
    if (idx >= n4) return;
    float m = mask[(idx * 4) >> 9];
    float4 v = *(const float4*)(hseq + (size_t)idx * 4);
    v.x *= m; v.y *= m; v.z *= m; v.w *= m;
    __nv_bfloat16 h0 = __float2bfloat16(v.x), h1 = __float2bfloat16(v.y);
    __nv_bfloat16 h2 = __float2bfloat16(v.z), h3 = __float2bfloat16(v.w);
    *(__nv_bfloat162*)(hi + (size_t)idx * 4)     = __halves2bfloat162(h0, h1);
    *(__nv_bfloat162*)(hi + (size_t)idx * 4 + 2) = __halves2bfloat162(h2, h3);
    *(__nv_bfloat162*)(lo + (size_t)idx * 4)     =
        __halves2bfloat162(__float2bfloat16(v.x - __bfloat162float(h0)),
                           __float2bfloat16(v.y - __bfloat162float(h1)));
    *(__nv_bfloat162*)(lo + (size_t)idx * 4 + 2) =
        __halves2bfloat162(__float2bfloat16(v.z - __bfloat162float(h2)),
                           __float2bfloat16(v.w - __bfloat162float(h3)));
}

__global__ void init_kernel(const float* __restrict__ b_lstm,
                            float* __restrict__ b4,
                            float* __restrict__ h0,
                            unsigned* __restrict__ bar,
                            unsigned* __restrict__ q,
                            unsigned* __restrict__ ready) {
    int idx = blockIdx.x * blockDim.x + threadIdx.x;
    if (idx == 0) { *bar = 0u; *q = 0u; }
    if (idx < T_) ready[idx] = 0u;
    if (idx < G4_) b4[idx] = b_lstm[(idx & 3) * U_ + (idx >> 2)];
    if (idx < B_ * U_) h0[idx] = 0.0f;
}

// ---------------------------------------------------------------------------
// Stand-alone tensor GEMM (BKT=64) for phase 3. (R11, frozen)
// ---------------------------------------------------------------------------
__global__ __launch_bounds__(256, 1) void tgemm2(
    const __nv_bfloat16* __restrict__ Ah, const __nv_bfloat16* __restrict__ Al,
    const __nv_bfloat16* __restrict__ Bh, const __nv_bfloat16* __restrict__ Bl,
    const float* __restrict__ bias, float* __restrict__ C,
    int M, int N, int K, int relu)
{
    extern __shared__ __nv_bfloat16 ts[];

    int tid  = threadIdx.x;
    int warp = tid >> 5, lane = tid & 31;
    int wm = warp >> 1, wn = warp & 1;
    int m0 = blockIdx.y * 128, n0 = blockIdx.x * 128;

    float acc[2][8][4];
    #pragma unroll
    for (int i = 0; i < 2; i++)
        #pragma unroll
        for (int j = 0; j < 8; j++)
            #pragma unroll
            for (int q = 0; q < 4; q++) acc[i][j][q] = 0.0f;

    int a_r = (lane & 15);
    int a_c = (lane >> 4) * 8;
    int aoffA = (wm * 32 + a_r) * APITCH + a_c;
    int aoffB = a_r * BPITCH + wn * 64 + a_c;

    int KT = K / BKT;

    auto load_stage = [&](int kt, int s) {
        __nv_bfloat16* st = ts + s * STAGE_ELEM;
        __nv_bfloat16* sAh = st;
        __nv_bfloat16* sAl = st + SA_ELEM;
        __nv_bfloat16* sBh = st + 2 * SA_ELEM;
        __nv_bfloat16* sBl = st + 2 * SA_ELEM + SB_ELEM;
        int k0 = kt * BKT;
        const __nv_bfloat16* gAh = Ah + (size_t)m0 * K + k0;
        const __nv_bfloat16* gAl = Al + (size_t)m0 * K + k0;
        const __nv_bfloat16* gBh = Bh + (size_t)k0 * N + n0;
        const __nv_bfloat16* gBl = Bl + (size_t)k0 * N + n0;
        #pragma unroll
        for (int j = 0; j < 4; j++) {
            int ca = tid + j * 256;
            int ar = ca >> 3, as = ca & 7;
            cpa16(smem_u32(sAh + ar * APITCH + as * 8), gAh + (size_t)ar * K + as * 8);
            cpa16(smem_u32(sAl + ar * APITCH + as * 8), gAl + (size_t)ar * K + as * 8);
            int br = ca >> 4, bs = ca & 15;
            cpa16(smem_u32(sBh + br * BPITCH + bs * 8), gBh + (size_t)br * N + bs * 8);
            cpa16(smem_u32(sBl + br * BPITCH + bs * 8), gBl + (size_t)br * N + bs * 8);
        }
    };

    load_stage(0, 0);
    cpa_commit();
    cpa_wait0();
    __syncthreads();

    for (int kt = 0; kt < KT; kt++) {
        int cur = kt & 1;
        if (kt + 1 < KT) {
            load_stage(kt + 1, cur ^ 1);
            cpa_commit();
        }

        __nv_bfloat16* st = ts + cur * STAGE_ELEM;
        uint32_t aAh = smem_u32(st + aoffA);
        uint32_t aAl = smem_u32(st + SA_ELEM + aoffA);
        uint32_t aBh = smem_u32(st + 2 * SA_ELEM + aoffB);
        uint32_t aBl = smem_u32(st + 2 * SA_ELEM + SB_ELEM + aoffB);

        #pragma unroll
        for (int kk = 0; kk < 4; kk++) {
            uint32_t Ahf[2][4], Alf[2][4];
            #pragma unroll
            for (int mt = 0; mt < 2; mt++) {
                uint32_t off = (mt * 16) * APITCH * 2 + kk * 16 * 2;
                ldsm_x4(Ahf[mt][0], Ahf[mt][1], Ahf[mt][2], Ahf[mt][3], aAh + off);
                ldsm_x4(Alf[mt][0], Alf[mt][1], Alf[mt][2], Alf[mt][3], aAl + off);
            }
            uint32_t Bhf[8][2], Blf[8][2];
            #pragma unroll
            for (int p = 0; p < 4; p++) {
                uint32_t off = (kk * 16) * BPITCH * 2 + p * 16 * 2;
                ldsm_x4t(Bhf[2*p][0], Bhf[2*p][1], Bhf[2*p+1][0], Bhf[2*p+1][1], aBh + off);
                ldsm_x4t(Blf[2*p][0], Blf[2*p][1], Blf[2*p+1][0], Blf[2*p+1][1], aBl + off);
            }
            #pragma unroll
            for (int mt = 0; mt < 2; mt++)
                #pragma unroll
                for (int nt = 0; nt < 8; nt++) {
                    mma_bf16(acc[mt][nt], Ahf[mt], Bhf[nt]);
                    mma_bf16(acc[mt][nt], Ahf[mt], Blf[nt]);
                    mma_bf16(acc[mt][nt], Alf[mt], Bhf[nt]);
                }
        }

        if (kt + 1 < KT) cpa_wait0();
        __syncthreads();
    }

    int crow = lane >> 2;
    int ccol = (lane & 3) * 2;
    #pragma unroll
    for (int mt = 0; mt < 2; mt++) {
        int r0 = m0 + wm * 32 + mt * 16 + crow;
        #pragma unroll
        for (int nt = 0; nt < 8; nt++) {
            int cglob = n0 + wn * 64 + nt * 8 + ccol;
            float b0 = bias[cglob], b1 = bias[cglob + 1];
            float2 v0 = { acc[mt][nt][0] + b0, acc[mt][nt][1] + b1 };
            float2 v1 = { acc[mt][nt][2] + b0, acc[mt][nt][3] + b1 };
            if (relu) {
                v0.x = fmaxf(v0.x, 0.f); v0.y = fmaxf(v0.y, 0.f);
                v1.x = fmaxf(v1.x, 0.f); v1.y = fmaxf(v1.y, 0.f);
            }
            *(float2*)(C + (size_t)r0 * N + cglob)       = v0;
            *(float2*)(C + (size_t)(r0 + 8) * N + cglob) = v1;
        }
    }
}

// ---------------------------------------------------------------------------
// FUSED phase1+phase2 (R11 structure). Recurrence staging now BATCH-MAJOR:
// Hs[b][kk] pitch 68 -> staging is one clean STS.128 per float4 (was 4
// scalar STS with 4-way bank conflicts). Thread (tx,ty) owns batches
// {ty, ty+64}; reads Hs[ty*68+kk], Hs[(ty+64)*68+kk] (conflict-free
// broadcasts: banks 4*ty+kk distinct, +64 row aliases to same banks).
// GEMM role byte-identical to R11.
// ---------------------------------------------------------------------------
__global__ __launch_bounds__(512, 1) void fused_p12(
    const __nv_bfloat16* __restrict__ Ah, const __nv_bfloat16* __restrict__ Al,
    const __nv_bfloat16* __restrict__ Bh, const __nv_bfloat16* __restrict__ Bl,
    const float* __restrict__ b4, float* xz,
    const float* __restrict__ h0, const float* __restrict__ Wrec,
    float* hseq, unsigned* bar, unsigned* q, unsigned* ready)
{
    extern __shared__ char smemc[];
    int tid = threadIdx.x;

    if (tid < 256) {
        // ------------------ RECURRENCE ROLE (bar 1) -----------------------
        float* Ws = (float*)(smemc + FS_WS);     // [512][16]
        float* Hs = (float*)(smemc + FS_HS);     // [B_][HP2]
        int rtid = tid;
        int blk = blockIdx.x;
        int n0 = blk * 16;
        int tx = rtid & 3;
        int ty = rtid >> 2;                      // 0..63; batches ty, ty+64
        int u  = blk * 4 + tx;

        for (int l = rtid; l < 512 * 4; l += 256) {
            int row = l >> 2, c4 = l & 3;
            *(float4*)&Ws[row * 16 + c4 * 4] =
                *(const float4*)(Wrec + (size_t)row * G4_ + n0 + c4 * 4);
        }

        float creg0 = 0.0f, creg1 = 0.0f;
        const float* hp = h0;

        for (int t = 0; t < T_; t++) {
            float acc[2][4];
            #pragma unroll
            for (int i = 0; i < 2; i++)
                #pragma unroll
                for (int j = 0; j < 4; j++) acc[i][j] = 0.0f;

            for (int k0 = 0; k0 < U_; k0 += KC) {
                // stage h chunk batch-major: Hs[b][k4*4..] as STS.128
                #pragma unroll
                for (int i = 0; i < 8; i++) {
                    int l = rtid + i * 256;      // 0..2047 float4
                    int b = l >> 4, k4 = l & 15;
                    float4 v = __ldcg((const float4*)(hp + (size_t)b * U_ + k0 + k4 * 4));
                    *(float4*)&Hs[b * HP2 + k4 * 4] = v;
                }
                BARR1;

                #pragma unroll 16
                for (int kk = 0; kk < KC; kk++) {
                    float4 wv = *(float4*)&Ws[(k0 + kk) * 16 + tx * 4];
                    float ha = Hs[ty * HP2 + kk];
                    float hb = Hs[(ty + 64) * HP2 + kk];
                    acc[0][0] += ha * wv.x; acc[0][1] += ha * wv.y;
                    acc[0][2] += ha * wv.z; acc[0][3] += ha * wv.w;
                    acc[1][0] += hb * wv.x; acc[1][1] += hb * wv.y;
                    acc[1][2] += hb * wv.z; acc[1][3] += hb * wv.w;
                }
                BARR1;
            }

            if (rtid == 0) {
                while (((volatile unsigned*)ready)[t] < 16u) {}
                __threadfence();
            }
            BARR1;

            #pragma unroll
            for (int i = 0; i < 2; i++) {
                int b = ty + 64 * i;
                const float4* xzp = (const float4*)(xz + ((size_t)t * B_ + b) * G4_ + n0 + tx * 4);
                float4 xv = __ldcg(xzp);
                float zi = acc[i][0] + xv.x;
                float zf = acc[i][1] + xv.y;
                float zg = acc[i][2] + xv.z;
                float zo = acc[i][3] + xv.w;
                float ig = 1.0f / (1.0f + expf(-zi));
                float fg = 1.0f / (1.0f + expf(-zf));
                float gg = tanhf(zg);
                float og = 1.0f / (1.0f + expf(-zo));
                float cp = i ? creg1 : creg0;
                float cn = fg * cp + ig * gg;
                if (i) creg1 = cn; else creg0 = cn;
                hseq[((size_t)t * B_ + b) * U_ + u] = og * tanhf(cn);
            }

            __threadfence();
            BARR1;
            if (rtid == 0) {
                atomicAdd(bar, 1u);
                unsigned target = (unsigned)RBLK * (unsigned)(t + 1);
                while (*(volatile unsigned*)bar < target) {}
            }
            BARR1;

            hp = hseq + (size_t)t * B_ * U_;
        }
    } else {
        // ------------------ GEMM ROLE (phase 1, BKT=64, bar 2) ------------
        __nv_bfloat16* ts = (__nv_bfloat16*)smemc;
        volatile int* sm_tile = (volatile int*)(smemc + FS_TILE);
        int wtid = tid - 256;
        int warp = wtid >> 5, lane = wtid & 31;
        int wm = warp >> 1, wn = warp & 1;

        int a_r = (lane & 15);
        int a_c = (lane >> 4) * 8;
        int aoffA = (wm * 32 + a_r) * APITCH + a_c;
        int aoffB = a_r * BPITCH + wn * 64 + a_c;

        const int Kg = F_, Ng = G4_, KT = F_ / BKT;

        for (;;) {
            if (wtid == 0) *sm_tile = (int)atomicAdd(q, 1u);
            BARR2;
            int tile = *sm_tile;
            BARR2;
            if (tile >= P1_TILES) break;
            int m0 = (tile >> 4) * 128;     // t-major: tile = t*16 + ncol
            int n0 = (tile & 15) * 128;

            float acc[2][8][4];
            #pragma unroll
            for (int i = 0; i < 2; i++)
                #pragma unroll
                for (int j = 0; j < 8; j++)
                    #pragma unroll
                    for (int qq = 0; qq < 4; qq++) acc[i][j][qq] = 0.0f;

            auto load_stage = [&](int kt, int s) {
                __nv_bfloat16* st = ts + s * STAGE_ELEM;
                __nv_bfloat16* sAh = st;
                __nv_bfloat16* sAl = st + SA_ELEM;
                __nv_bfloat16* sBh = st + 2 * SA_ELEM;
                __nv_bfloat16* sBl = st + 2 * SA_ELEM + SB_ELEM;
                int k0 = kt * BKT;
                const __nv_bfloat16* gAh = Ah + (size_t)m0 * Kg + k0;
                const __nv_bfloat16* gAl = Al + (size_t)m0 * Kg + k0;
                const __nv_bfloat16* gBh = Bh + (size_t)k0 * Ng + n0;
                const __nv_bfloat16* gBl = Bl + (size_t)k0 * Ng + n0;
                #pragma unroll
                for (int j = 0; j < 4; j++) {
                    int ca = wtid + j * 256;
                    int ar = ca >> 3, as = ca & 7;
                    cpa16(smem_u32(sAh + ar * APITCH + as * 8), gAh + (size_t)ar * Kg + as * 8);
                    cpa16(smem_u32(sAl + ar * APITCH + as * 8), gAl + (size_t)ar * Kg + as * 8);
                    int br = ca >> 4, bs = ca & 15;
                    cpa16(smem_u32(sBh + br * BPITCH + bs * 8), gBh + (size_t)br * Ng + bs * 8);
                    cpa16(smem_u32(sBl + br * BPITCH + bs * 8), gBl + (size_t)br * Ng + bs * 8);
                }
            };

            load_stage(0, 0);
            cpa_commit();
            cpa_wait0();
            BARR2;

            for (int kt = 0; kt < KT; kt++) {
                int cur = kt & 1;
                if (kt + 1 < KT) {
                    load_stage(kt + 1, cur ^ 1);
                    cpa_commit();
                }

                __nv_bfloat16* st = ts + cur * STAGE_ELEM;
                uint32_t aAh = smem_u32(st + aoffA);
                uint32_t aAl = smem_u32(st + SA_ELEM + aoffA);
                uint32_t aBh = smem_u32(st + 2 * SA_ELEM + aoffB);
                uint32_t aBl = smem_u32(st + 2 * SA_ELEM + SB_ELEM + aoffB);

                #pragma unroll
                for (int kk = 0; kk < 4; kk++) {
                    uint32_t Ahf[2][4], Alf[2][4];
                    #pragma unroll
                    for (int mt = 0; mt < 2; mt++) {
                        uint32_t off = (mt * 16) * APITCH * 2 + kk * 16 * 2;
                        ldsm_x4(Ahf[mt][0], Ahf[mt][1], Ahf[mt][2], Ahf[mt][3], aAh + off);
                        ldsm_x4(Alf[mt][0], Alf[mt][1], Alf[mt][2], Alf[mt][3], aAl + off);
                    }
                    uint32_t Bhf[8][2], Blf[8][2];
                    #pragma unroll
                    for (int p = 0; p < 4; p++) {
                        uint32_t off = (kk * 16) * BPITCH * 2 + p * 16 * 2;
                        ldsm_x4t(Bhf[2*p][0], Bhf[2*p][1], Bhf[2*p+1][0], Bhf[2*p+1][1], aBh + off);
                        ldsm_x4t(Blf[2*p][0], Blf[2*p][1], Blf[2*p+1][0], Blf[2*p+1][1], aBl + off);
                    }
                    #pragma unroll
                    for (int mt = 0; mt < 2; mt++)
                        #pragma unroll
                        for (int nt = 0; nt < 8; nt++) {
                            mma_bf16(acc[mt][nt], Ahf[mt], Bhf[nt]);
                            mma_bf16(acc[mt][nt], Ahf[mt], Blf[nt]);
                            mma_bf16(acc[mt][nt], Alf[mt], Bhf[nt]);
                        }
                }

                if (kt + 1 < KT) cpa_wait0();
                BARR2;
            }

            int crow = lane >> 2;
            int ccol = (lane & 3) * 2;
            #pragma unroll
            for (int mt = 0; mt < 2; mt++) {
                int r0 = m0 + wm * 32 + mt * 16 + crow;
                #pragma unroll
                for (int nt = 0; nt < 8; nt++) {
                    int cglob = n0 + wn * 64 + nt * 8 + ccol;
                    float b0 = b4[cglob], b1 = b4[cglob + 1];
                    float2 v0 = { acc[mt][nt][0] + b0, acc[mt][nt][1] + b1 };
                    float2 v1 = { acc[mt][nt][2] + b0, acc[mt][nt][3] + b1 };
                    *(float2*)(xz + (size_t)r0 * Ng + cglob)       = v0;
                    *(float2*)(xz + (size_t)(r0 + 8) * Ng + cglob) = v1;
                }
            }

            __threadfence();
            BARR2;
            if (wtid == 0) atomicAdd(ready + (m0 >> 7), 1u);
        }
    }
}

// ---------------------------------------------------------------------------
// In-place row softmax (1024 cols, one block/row).
// ---------------------------------------------------------------------------
__global__ __launch_bounds__(256) void softmax_kernel(float* __restrict__ out) {
    __shared__ float red[8];
    int tid = threadIdx.x;
    float* p = out + (size_t)blockIdx.x * CODES_;

    float4 v = *(float4*)(p + tid * 4);
    float m = fmaxf(fmaxf(v.x, v.y), fmaxf(v.z, v.w));
    #pragma unroll
    for (int o = 16; o > 0; o >>= 1) m = fmaxf(m, __shfl_xor_sync(0xFFFFFFFFu, m, o));
    if ((tid & 31) == 0) red[tid >> 5] = m;
    __syncthreads();
    float bm = red[0];
    #pragma unroll
    for (int i = 1; i < 8; i++) bm = fmaxf(bm, red[i]);
    __syncthreads();

    v.x = expf(v.x - bm); v.y = expf(v.y - bm);
    v.z = expf(v.z - bm); v.w = expf(v.w - bm);
    float s = v.x + v.y + v.z + v.w;
    #pragma unroll
    for (int o = 16; o > 0; o >>= 1) s += __shfl_xor_sync(0xFFFFFFFFu, s, o);
    if ((tid & 31) == 0) red[tid >> 5] = s;
    __syncthreads();
    float bs = red[0];
    #pragma unroll
    for (int i = 1; i < 8; i++) bs += red[i];
    float inv = 1.0f / bs;
    v.x *= inv; v.y *= inv; v.z *= inv; v.w *= inv;
    *(float4*)(p + tid * 4) = v;
}

// ---------------------------------------------------------------------------
// Launch
// ---------------------------------------------------------------------------
extern "C" void kernel_launch(void* const* d_in, const int* in_sizes, int n_in,
                              void* d_out, int out_size) {
    const float* x       = (const float*)d_in[0];
    const float* mask    = (const float*)d_in[1];
    const float* W_in    = (const float*)d_in[2];
    const float* W_rec   = (const float*)d_in[3];
    const float* b_lstm  = (const float*)d_in[4];
    const float* W_dense = (const float*)d_in[5];
    const float* b_dense = (const float*)d_in[6];
    float* out = (float*)d_out;

    float *xz, *hseq, *h0, *Wrec4, *b4;
    unsigned *bar, *q, *ready;
    __nv_bfloat16 *xh, *xl, *Wih, *Wil, *Wdh, *Wdl, *hh, *hl;
    cudaGetSymbolAddress((void**)&xz,    g_xz);
    cudaGetSymbolAddress((void**)&hseq,  g_hseq);
    cudaGetSymbolAddress((void**)&h0,    g_h0);
    cudaGetSymbolAddress((void**)&Wrec4, g_Wrec4);
    cudaGetSymbolAddress((void**)&b4,    g_b4);
    cudaGetSymbolAddress((void**)&bar,   g_bar);
    cudaGetSymbolAddress((void**)&q,     g_q);
    cudaGetSymbolAddress((void**)&ready, g_ready);
    cudaGetSymbolAddress((void**)&xh,    g_xh);
    cudaGetSymbolAddress((void**)&xl,    g_xl);
    cudaGetSymbolAddress((void**)&Wih,   g_Wih);
    cudaGetSymbolAddress((void**)&Wil,   g_Wil);
    cudaGetSymbolAddress((void**)&Wdh,   g_Wdh);
    cudaGetSymbolAddress((void**)&Wdl,   g_Wdl);
    cudaGetSymbolAddress((void**)&hh,    g_hh);
    cudaGetSymbolAddress((void**)&hl,    g_hl);

    cudaFuncSetAttribute(fused_p12,
                         cudaFuncAttributeMaxDynamicSharedMemorySize, FUSED_SMEM);
    cudaFuncSetAttribute(tgemm2,
                         cudaFuncAttributeMaxDynamicSharedMemorySize, GEMM_SMEM);

    // Pre-passes
    reorder_gates<<<(U_ * G4_ + 255) / 256, 256>>>(W_rec, Wrec4, U_ * G4_);
    reorder_split<<<(F_ * G4_ + 255) / 256, 256>>>(W_in, Wih, Wil, F_ * G4_);
    convert_split<<<(U_ * CODES_ / 4 + 255) / 256, 256>>>(W_dense, Wdh, Wdl, U_ * CODES_ / 4);
    convert_split<<<((int)((size_t)ROWS_ * F_ / 4) + 255) / 256, 256>>>(x, xh, xl, (int)((size_t)ROWS_ * F_ / 4));
    init_kernel<<<(B_ * U_ + 255) / 256, 256>>>(b_lstm, b4, h0, bar, q, ready);

    // Phase 1+2 fused
    fused_p12<<<RBLK, 512, FUSED_SMEM>>>(
        xh, xl, Wih, Wil, b4, xz, h0, Wrec4, hseq, bar, q, ready);

    // Phase 2.5: masked h -> bf16 hi/lo
    convert_mask<<<((int)((size_t)ROWS_ * U_ / 4) + 255) / 256, 256>>>(
        hseq, mask, hh, hl, (int)((size_t)ROWS_ * U_ / 4));

    // Phase 3: logits = relu(masked_h @ W_dense + b_dense)
    tgemm2<<<dim3(CODES_ / 128, ROWS_ / 128), 256, GEMM_SMEM>>>(
        hh, hl, Wdh, Wdl, b_dense, out, ROWS_, CODES_, U_, 1);

    // Phase 4: softmax
    softmax_kernel<<<ROWS_, 256>>>(out);
}

// round 16
// speedup vs baseline: 1.4821x; 1.1806x over previous
#include <cuda_runtime.h>
#include <cuda_bf16.h>
#include <math.h>
#include <stdint.h>

// Problem constants
#define T_   256
#define B_   128
#define F_   1024
#define U_   512
#define G4_  2048   // 4*U
#define CODES_ 1024
#define ROWS_ 32768 // T*B

#define RBLK 128    // fused persistent blocks (1/SM)
#define KC   32     // recurrence K chunk (double-buffered)
#define HP3  36     // Hs row pitch, batch-major [b][kk] (KC+4)

// Tensor GEMM tile: 128x128, K-chunk 64
#define BKT  64
#define APITCH 72
#define BPITCH 136
#define SA_ELEM (128 * APITCH)                  // 9216
#define SB_ELEM (BKT * BPITCH)                  // 8704
#define STAGE_ELEM (2 * SA_ELEM + 2 * SB_ELEM)  // 35840
#define GEMM_SMEM (2 * STAGE_ELEM * 2)          // 143360 B

// Fused kernel smem layout (bytes)
#define FS_WS   GEMM_SMEM                        // 143360: W_rec slice (512x16 f32)
#define FS_HS   (FS_WS + 512 * 16 * 4)           // 176128: Hs double buffer
#define HSBUF_B (B_ * HP3 * 4)                   // 18432 per buffer
#define FS_TILE (FS_HS + 2 * HSBUF_B)            // 212992: tile broadcast slot
#define FUSED_SMEM (FS_TILE + 16)                // 213008

#define P1_TILES (T_ * (G4_ / 128))              // 4096 tiles, 16 per timestep

#define BARR1 asm volatile("bar.sync 1, 256;" ::: "memory")
#define BARR2 asm volatile("bar.sync 2, 256;" ::: "memory")

// ---------------------------------------------------------------------------
// Scratch
// ---------------------------------------------------------------------------
__device__ float g_xz   [(size_t)ROWS_ * G4_];
__device__ float g_hseq [(size_t)ROWS_ * U_];
__device__ float g_h0   [B_ * U_];
__device__ float g_Wrec4[(size_t)U_ * G4_];
__device__ float g_b4   [G4_];
__device__ unsigned g_bar;
__device__ unsigned g_q;
__device__ unsigned g_ready[T_];

__device__ __nv_bfloat16 g_xh [(size_t)ROWS_ * F_];
__device__ __nv_bfloat16 g_xl [(size_t)ROWS_ * F_];
__device__ __nv_bfloat16 g_Wih[(size_t)F_ * G4_];
__device__ __nv_bfloat16 g_Wil[(size_t)F_ * G4_];
__device__ __nv_bfloat16 g_Wdh[(size_t)U_ * CODES_];
__device__ __nv_bfloat16 g_Wdl[(size_t)U_ * CODES_];
__device__ __nv_bfloat16 g_hh [(size_t)ROWS_ * U_];
__device__ __nv_bfloat16 g_hl [(size_t)ROWS_ * U_];

// ---------------------------------------------------------------------------
// Helpers
// ---------------------------------------------------------------------------
__device__ __forceinline__ uint32_t smem_u32(const void* p) {
    return (uint32_t)__cvta_generic_to_shared(p);
}
__device__ __forceinline__ void cpa16(uint32_t dst, const void* src) {
    asm volatile("cp.async.cg.shared.global [%0], [%1], 16;\n" :: "r"(dst), "l"(src));
}
__device__ __forceinline__ void cpa_commit() { asm volatile("cp.async.commit_group;\n" ::); }
__device__ __forceinline__ void cpa_wait0()  { asm volatile("cp.async.wait_group 0;\n" ::); }
__device__ __forceinline__ void ldsm_x4(uint32_t& r0, uint32_t& r1, uint32_t& r2, uint32_t& r3, uint32_t a) {
    asm volatile("ldmatrix.sync.aligned.m8n8.x4.shared.b16 {%0,%1,%2,%3},[%4];"
                 : "=r"(r0), "=r"(r1), "=r"(r2), "=r"(r3) : "r"(a));
}
__device__ __forceinline__ void ldsm_x4t(uint32_t& r0, uint32_t& r1, uint32_t& r2, uint32_t& r3, uint32_t a) {
    asm volatile("ldmatrix.sync.aligned.m8n8.x4.trans.shared.b16 {%0,%1,%2,%3},[%4];"
                 : "=r"(r0), "=r"(r1), "=r"(r2), "=r"(r3) : "r"(a));
}
__device__ __forceinline__ void mma_bf16(float c[4], const uint32_t a[4], const uint32_t b[2]) {
    asm volatile(
        "mma.sync.aligned.m16n8k16.row.col.f32.bf16.bf16.f32 "
        "{%0,%1,%2,%3},{%4,%5,%6,%7},{%8,%9},{%0,%1,%2,%3};"
        : "+f"(c[0]), "+f"(c[1]), "+f"(c[2]), "+f"(c[3])
        : "r"(a[0]), "r"(a[1]), "r"(a[2]), "r"(a[3]), "r"(b[0]), "r"(b[1]));
}

// ---------------------------------------------------------------------------
// Pre-pass kernels
// ---------------------------------------------------------------------------
__global__ void reorder_gates(const float* __restrict__ W, float* __restrict__ W4, int total) {
    int idx = blockIdx.x * blockDim.x + threadIdx.x;
    if (idx >= total) return;
    int col = idx & (G4_ - 1);
    int k   = idx >> 11;
    W4[idx] = W[(size_t)k * G4_ + (col & 3) * U_ + (col >> 2)];
}

__global__ void reorder_split(const float* __restrict__ W,
                              __nv_bfloat16* __restrict__ hi,
                              __nv_bfloat16* __restrict__ lo, int total) {
    int idx = blockIdx.x * blockDim.x + threadIdx.x;
    if (idx >= total) return;
    int col = idx & (G4_ - 1);
    int k   = idx >> 11;
    float v = W[(size_t)k * G4_ + (col & 3) * U_ + (col >> 2)];
    __nv_bfloat16 h = __float2bfloat16(v);
    hi[idx] = h;
    lo[idx] = __float2bfloat16(v - __bfloat162float(h));
}

__global__ void convert_split(const float* __restrict__ src,
                              __nv_bfloat16* __restrict__ hi,
                              __nv_bfloat16* __restrict__ lo, int n4) {
    int idx = blockIdx.x * blockDim.x + threadIdx.x;
    if (idx >= n4) return;
    float4 v = *(const float4*)(src + (size_t)idx * 4);
    __nv_bfloat16 h0 = __float2bfloat16(v.x), h1 = __float2bfloat16(v.y);
    __nv_bfloat16 h2 = __float2bfloat16(v.z), h3 = __float2bfloat16(v.w);
    *(__nv_bfloat162*)(hi + (size_t)idx * 4)     = __halves2bfloat162(h0, h1);
    *(__nv_bfloat162*)(hi + (size_t)idx * 4 + 2) = __halves2bfloat162(h2, h3);
    *(__nv_bfloat162*)(lo + (size_t)idx * 4)     =
        __halves2bfloat162(__float2bfloat16(v.x - __bfloat162float(h0)),
                           __float2bfloat16(v.y - __bfloat162float(h1)));
    *(__nv_bfloat162*)(lo + (size_t)idx * 4 + 2) =
        __halves2bfloat162(__float2bfloat16(v.z - __bfloat162float(h2)),
                           __float2bfloat16(v.w - __bfloat162float(h3)));
}

__global__ void convert_mask(const float* __restrict__ hseq,
                             const float* __restrict__ mask,
                             __nv_bfloat16* __restrict__ hi,
                             __nv_bfloat16* __restrict__ lo, int n4) {
    int idx = blockIdx.x * blockDim.x + threadIdx.x;
    if (idx >= n4) return;
    float m = mask[(idx * 4) >> 9];
    float4 v = *(const float4*)(hseq + (size_t)idx * 4);
    v.x *= m; v.y *= m; v.z *= m; v.w *= m;
    __nv_bfloat16 h0 = __float2bfloat16(v.x), h1 = __float2bfloat16(v.y);
    __nv_bfloat16 h2 = __float2bfloat16(v.z), h3 = __float2bfloat16(v.w);
    *(__nv_bfloat162*)(hi + (size_t)idx * 4)     = __halves2bfloat162(h0, h1);
    *(__nv_bfloat162*)(hi + (size_t)idx * 4 + 2) = __halves2bfloat162(h2, h3);
    *(__nv_bfloat162*)(lo + (size_t)idx * 4)     =
        __halves2bfloat162(__float2bfloat16(v.x - __bfloat162float(h0)),
                           __float2bfloat16(v.y - __bfloat162float(h1)));
    *(__nv_bfloat162*)(lo + (size_t)idx * 4 + 2) =
        __halves2bfloat162(__float2bfloat16(v.z - __bfloat162float(h2)),
                           __float2bfloat16(v.w - __bfloat162float(h3)));
}

__global__ void init_kernel(const float* __restrict__ b_lstm,
                            float* __restrict__ b4,
                            float* __restrict__ h0,
                            unsigned* __restrict__ bar,
                            unsigned* __restrict__ q,
                            unsigned* __restrict__ ready) {
    int idx = blockIdx.x * blockDim.x + threadIdx.x;
    if (idx == 0) { *bar = 0u; *q = 0u; }
    if (idx < T_) ready[idx] = 0u;
    if (idx < G4_) b4[idx] = b_lstm[(idx & 3) * U_ + (idx >> 2)];
    if (idx < B_ * U_) h0[idx] = 0.0f;
}

// ---------------------------------------------------------------------------
// Stand-alone tensor GEMM (BKT=64) for phase 3. (R11/R15, frozen)
// ---------------------------------------------------------------------------
__global__ __launch_bounds__(256, 1) void tgemm2(
    const __nv_bfloat16* __restrict__ Ah, const __nv_bfloat16* __restrict__ Al,
    const __nv_bfloat16* __restrict__ Bh, const __nv_bfloat16* __restrict__ Bl,
    const float* __restrict__ bias, float* __restrict__ C,
    int M, int N, int K, int relu)
{
    extern __shared__ __nv_bfloat16 ts[];

    int tid  = threadIdx.x;
    int warp = tid >> 5, lane = tid & 31;
    int wm = warp >> 1, wn = warp & 1;
    int m0 = blockIdx.y * 128, n0 = blockIdx.x * 128;

    float acc[2][8][4];
    #pragma unroll
    for (int i = 0; i < 2; i++)
        #pragma unroll
        for (int j = 0; j < 8; j++)
            #pragma unroll
            for (int q = 0; q < 4; q++) acc[i][j][q] = 0.0f;

    int a_r = (lane & 15);
    int a_c = (lane >> 4) * 8;
    int aoffA = (wm * 32 + a_r) * APITCH + a_c;
    int aoffB = a_r * BPITCH + wn * 64 + a_c;

    int KT = K / BKT;

    auto load_stage = [&](int kt, int s) {
        __nv_bfloat16* st = ts + s * STAGE_ELEM;
        __nv_bfloat16* sAh = st;
        __nv_bfloat16* sAl = st + SA_ELEM;
        __nv_bfloat16* sBh = st + 2 * SA_ELEM;
        __nv_bfloat16* sBl = st + 2 * SA_ELEM + SB_ELEM;
        int k0 = kt * BKT;
        const __nv_bfloat16* gAh = Ah + (size_t)m0 * K + k0;
        const __nv_bfloat16* gAl = Al + (size_t)m0 * K + k0;
        const __nv_bfloat16* gBh = Bh + (size_t)k0 * N + n0;
        const __nv_bfloat16* gBl = Bl + (size_t)k0 * N + n0;
        #pragma unroll
        for (int j = 0; j < 4; j++) {
            int ca = tid + j * 256;
            int ar = ca >> 3, as = ca & 7;
            cpa16(smem_u32(sAh + ar * APITCH + as * 8), gAh + (size_t)ar * K + as * 8);
            cpa16(smem_u32(sAl + ar * APITCH + as * 8), gAl + (size_t)ar * K + as * 8);
            int br = ca >> 4, bs = ca & 15;
            cpa16(smem_u32(sBh + br * BPITCH + bs * 8), gBh + (size_t)br * N + bs * 8);
            cpa16(smem_u32(sBl + br * BPITCH + bs * 8), gBl + (size_t)br * N + bs * 8);
        }
    };

    load_stage(0, 0);
    cpa_commit();
    cpa_wait0();
    __syncthreads();

    for (int kt = 0; kt < KT; kt++) {
        int cur = kt & 1;
        if (kt + 1 < KT) {
            load_stage(kt + 1, cur ^ 1);
            cpa_commit();
        }

        __nv_bfloat16* st = ts + cur * STAGE_ELEM;
        uint32_t aAh = smem_u32(st + aoffA);
        uint32_t aAl = smem_u32(st + SA_ELEM + aoffA);
        uint32_t aBh = smem_u32(st + 2 * SA_ELEM + aoffB);
        uint32_t aBl = smem_u32(st + 2 * SA_ELEM + SB_ELEM + aoffB);

        #pragma unroll
        for (int kk = 0; kk < 4; kk++) {
            uint32_t Ahf[2][4], Alf[2][4];
            #pragma unroll
            for (int mt = 0; mt < 2; mt++) {
                uint32_t off = (mt * 16) * APITCH * 2 + kk * 16 * 2;
                ldsm_x4(Ahf[mt][0], Ahf[mt][1], Ahf[mt][2], Ahf[mt][3], aAh + off);
                ldsm_x4(Alf[mt][0], Alf[mt][1], Alf[mt][2], Alf[mt][3], aAl + off);
            }
            uint32_t Bhf[8][2], Blf[8][2];
            #pragma unroll
            for (int p = 0; p < 4; p++) {
                uint32_t off = (kk * 16) * BPITCH * 2 + p * 16 * 2;
                ldsm_x4t(Bhf[2*p][0], Bhf[2*p][1], Bhf[2*p+1][0], Bhf[2*p+1][1], aBh + off);
                ldsm_x4t(Blf[2*p][0], Blf[2*p][1], Blf[2*p+1][0], Blf[2*p+1][1], aBl + off);
            }
            #pragma unroll
            for (int mt = 0; mt < 2; mt++)
                #pragma unroll
                for (int nt = 0; nt < 8; nt++) {
                    mma_bf16(acc[mt][nt], Ahf[mt], Bhf[nt]);
                    mma_bf16(acc[mt][nt], Ahf[mt], Blf[nt]);
                    mma_bf16(acc[mt][nt], Alf[mt], Bhf[nt]);
                }
        }

        if (kt + 1 < KT) cpa_wait0();
        __syncthreads();
    }

    int crow = lane >> 2;
    int ccol = (lane & 3) * 2;
    #pragma unroll
    for (int mt = 0; mt < 2; mt++) {
        int r0 = m0 + wm * 32 + mt * 16 + crow;
        #pragma unroll
        for (int nt = 0; nt < 8; nt++) {
            int cglob = n0 + wn * 64 + nt * 8 + ccol;
            float b0 = bias[cglob], b1 = bias[cglob + 1];
            float2 v0 = { acc[mt][nt][0] + b0, acc[mt][nt][1] + b1 };
            float2 v1 = { acc[mt][nt][2] + b0, acc[mt][nt][3] + b1 };
            if (relu) {
                v0.x = fmaxf(v0.x, 0.f); v0.y = fmaxf(v0.y, 0.f);
                v1.x = fmaxf(v1.x, 0.f); v1.y = fmaxf(v1.y, 0.f);
            }
            *(float2*)(C + (size_t)r0 * N + cglob)       = v0;
            *(float2*)(C + (size_t)(r0 + 8) * N + cglob) = v1;
        }
    }
}

// ---------------------------------------------------------------------------
// FUSED phase1+phase2 (R15 structure). Recurrence staging now DOUBLE-BUFFERED
// via cp.async (KC=32): chunk c+1's L2 loads overlap chunk c's FFMA compute,
// removing the exposed L2 latency from the serial chain. Batch-major layout
// (pitch 36) keeps stores async and reads conflict-free broadcasts.
// GEMM role byte-identical to R15.
// ---------------------------------------------------------------------------
__global__ __launch_bounds__(512, 1) void fused_p12(
    const __nv_bfloat16* __restrict__ Ah, const __nv_bfloat16* __restrict__ Al,
    const __nv_bfloat16* __restrict__ Bh, const __nv_bfloat16* __restrict__ Bl,
    const float* __restrict__ b4, float* xz,
    const float* __restrict__ h0, const float* __restrict__ Wrec,
    float* hseq, unsigned* bar, unsigned* q, unsigned* ready)
{
    extern __shared__ char smemc[];
    int tid = threadIdx.x;

    if (tid < 256) {
        // ------------------ RECURRENCE ROLE (bar 1) -----------------------
        float* Ws  = (float*)(smemc + FS_WS);    // [512][16]
        float* Hs0 = (float*)(smemc + FS_HS);    // [B_][HP3]
        float* Hs1 = (float*)(smemc + FS_HS + HSBUF_B);
        int rtid = tid;
        int blk = blockIdx.x;
        int n0 = blk * 16;
        int tx = rtid & 3;
        int ty = rtid >> 2;                      // 0..63; batches ty, ty+64
        int u  = blk * 4 + tx;

        for (int l = rtid; l < 512 * 4; l += 256) {
            int row = l >> 2, c4 = l & 3;
            *(float4*)&Ws[row * 16 + c4 * 4] =
                *(const float4*)(Wrec + (size_t)row * G4_ + n0 + c4 * 4);
        }

        // per-thread staging indices: 4 cp.async of 16B per chunk
        // l = rtid + i*256 in [0,1024): b = l>>3 (0..127), k4 = l&7 (0..7)
        float creg0 = 0.0f, creg1 = 0.0f;
        const float* hp = h0;

        for (int t = 0; t < T_; t++) {
            float acc[2][4];
            #pragma unroll
            for (int i = 0; i < 2; i++)
                #pragma unroll
                for (int j = 0; j < 4; j++) acc[i][j] = 0.0f;

            // prologue: stage chunk 0 into Hs0
            #pragma unroll
            for (int i = 0; i < 4; i++) {
                int l = rtid + i * 256;
                int b = l >> 3, k4 = l & 7;
                cpa16(smem_u32(Hs0 + b * HP3 + k4 * 4),
                      hp + (size_t)b * U_ + k4 * 4);
            }
            cpa_commit();
            cpa_wait0();
            BARR1;

            #pragma unroll
            for (int c = 0; c < 16; c++) {
                float* cur = (c & 1) ? Hs1 : Hs0;
                float* nxt = (c & 1) ? Hs0 : Hs1;
                if (c < 15) {                    // stage chunk c+1 (async)
                    int k0n = (c + 1) * KC;
                    #pragma unroll
                    for (int i = 0; i < 4; i++) {
                        int l = rtid + i * 256;
                        int b = l >> 3, k4 = l & 7;
                        cpa16(smem_u32(nxt + b * HP3 + k4 * 4),
                              hp + (size_t)b * U_ + k0n + k4 * 4);
                    }
                    cpa_commit();
                }

                int k0 = c * KC;
                #pragma unroll
                for (int kk = 0; kk < KC; kk++) {
                    float4 wv = *(float4*)&Ws[(k0 + kk) * 16 + tx * 4];
                    float ha = cur[ty * HP3 + kk];
                    float hb = cur[(ty + 64) * HP3 + kk];
                    acc[0][0] += ha * wv.x; acc[0][1] += ha * wv.y;
                    acc[0][2] += ha * wv.z; acc[0][3] += ha * wv.w;
                    acc[1][0] += hb * wv.x; acc[1][1] += hb * wv.y;
                    acc[1][2] += hb * wv.z; acc[1][3] += hb * wv.w;
                }

                if (c < 15) cpa_wait0();
                BARR1;
            }

            if (rtid == 0) {
                while (((volatile unsigned*)ready)[t] < 16u) {}
                __threadfence();
            }
            BARR1;

            #pragma unroll
            for (int i = 0; i < 2; i++) {
                int b = ty + 64 * i;
                const float4* xzp = (const float4*)(xz + ((size_t)t * B_ + b) * G4_ + n0 + tx * 4);
                float4 xv = __ldcg(xzp);
                float zi = acc[i][0] + xv.x;
                float zf = acc[i][1] + xv.y;
                float zg = acc[i][2] + xv.z;
                float zo = acc[i][3] + xv.w;
                float ig = 1.0f / (1.0f + expf(-zi));
                float fg = 1.0f / (1.0f + expf(-zf));
                float gg = tanhf(zg);
                float og = 1.0f / (1.0f + expf(-zo));
                float cp = i ? creg1 : creg0;
                float cn = fg * cp + ig * gg;
                if (i) creg1 = cn; else creg0 = cn;
                hseq[((size_t)t * B_ + b) * U_ + u] = og * tanhf(cn);
            }

            __threadfence();
            BARR1;
            if (rtid == 0) {
                atomicAdd(bar, 1u);
                unsigned target = (unsigned)RBLK * (unsigned)(t + 1);
                while (*(volatile unsigned*)bar < target) {}
            }
            BARR1;

            hp = hseq + (size_t)t * B_ * U_;
        }
    } else {
        // ------------------ GEMM ROLE (phase 1, BKT=64, bar 2) ------------
        __nv_bfloat16* ts = (__nv_bfloat16*)smemc;
        volatile int* sm_tile = (volatile int*)(smemc + FS_TILE);
        int wtid = tid - 256;
        int warp = wtid >> 5, lane = wtid & 31;
        int wm = warp >> 1, wn = warp & 1;

        int a_r = (lane & 15);
        int a_c = (lane >> 4) * 8;
        int aoffA = (wm * 32 + a_r) * APITCH + a_c;
        int aoffB = a_r * BPITCH + wn * 64 + a_c;

        const int Kg = F_, Ng = G4_, KT = F_ / BKT;

        for (;;) {
            if (wtid == 0) *sm_tile = (int)atomicAdd(q, 1u);
            BARR2;
            int tile = *sm_tile;
            BARR2;
            if (tile >= P1_TILES) break;
            int m0 = (tile >> 4) * 128;     // t-major: tile = t*16 + ncol
            int n0 = (tile & 15) * 128;

            float acc[2][8][4];
            #pragma unroll
            for (int i = 0; i < 2; i++)
                #pragma unroll
                for (int j = 0; j < 8; j++)
                    #pragma unroll
                    for (int qq = 0; qq < 4; qq++) acc[i][j][qq] = 0.0f;

            auto load_stage = [&](int kt, int s) {
                __nv_bfloat16* st = ts + s * STAGE_ELEM;
                __nv_bfloat16* sAh = st;
                __nv_bfloat16* sAl = st + SA_ELEM;
                __nv_bfloat16* sBh = st + 2 * SA_ELEM;
                __nv_bfloat16* sBl = st + 2 * SA_ELEM + SB_ELEM;
                int k0 = kt * BKT;
                const __nv_bfloat16* gAh = Ah + (size_t)m0 * Kg + k0;
                const __nv_bfloat16* gAl = Al + (size_t)m0 * Kg + k0;
                const __nv_bfloat16* gBh = Bh + (size_t)k0 * Ng + n0;
                const __nv_bfloat16* gBl = Bl + (size_t)k0 * Ng + n0;
                #pragma unroll
                for (int j = 0; j < 4; j++) {
                    int ca = wtid + j * 256;
                    int ar = ca >> 3, as = ca & 7;
                    cpa16(smem_u32(sAh + ar * APITCH + as * 8), gAh + (size_t)ar * Kg + as * 8);
                    cpa16(smem_u32(sAl + ar * APITCH + as * 8), gAl + (size_t)ar * Kg + as * 8);
                    int br = ca >> 4, bs = ca & 15;
                    cpa16(smem_u32(sBh + br * BPITCH + bs * 8), gBh + (size_t)br * Ng + bs * 8);
                    cpa16(smem_u32(sBl + br * BPITCH + bs * 8), gBl + (size_t)br * Ng + bs * 8);
                }
            };

            load_stage(0, 0);
            cpa_commit();
            cpa_wait0();
            BARR2;

            for (int kt = 0; kt < KT; kt++) {
                int cur = kt & 1;
                if (kt + 1 < KT) {
                    load_stage(kt + 1, cur ^ 1);
                    cpa_commit();
                }

                __nv_bfloat16* st = ts + cur * STAGE_ELEM;
                uint32_t aAh = smem_u32(st + aoffA);
                uint32_t aAl = smem_u32(st + SA_ELEM + aoffA);
                uint32_t aBh = smem_u32(st + 2 * SA_ELEM + aoffB);
                uint32_t aBl = smem_u32(st + 2 * SA_ELEM + SB_ELEM + aoffB);

                #pragma unroll
                for (int kk = 0; kk < 4; kk++) {
                    uint32_t Ahf[2][4], Alf[2][4];
                    #pragma unroll
                    for (int mt = 0; mt < 2; mt++) {
                        uint32_t off = (mt * 16) * APITCH * 2 + kk * 16 * 2;
                        ldsm_x4(Ahf[mt][0], Ahf[mt][1], Ahf[mt][2], Ahf[mt][3], aAh + off);
                        ldsm_x4(Alf[mt][0], Alf[mt][1], Alf[mt][2], Alf[mt][3], aAl + off);
                    }
                    uint32_t Bhf[8][2], Blf[8][2];
                    #pragma unroll
                    for (int p = 0; p < 4; p++) {
                        uint32_t off = (kk * 16) * BPITCH * 2 + p * 16 * 2;
                        ldsm_x4t(Bhf[2*p][0], Bhf[2*p][1], Bhf[2*p+1][0], Bhf[2*p+1][1], aBh + off);
                        ldsm_x4t(Blf[2*p][0], Blf[2*p][1], Blf[2*p+1][0], Blf[2*p+1][1], aBl + off);
                    }
                    #pragma unroll
                    for (int mt = 0; mt < 2; mt++)
                        #pragma unroll
                        for (int nt = 0; nt < 8; nt++) {
                            mma_bf16(acc[mt][nt], Ahf[mt], Bhf[nt]);
                            mma_bf16(acc[mt][nt], Ahf[mt], Blf[nt]);
                            mma_bf16(acc[mt][nt], Alf[mt], Bhf[nt]);
                        }
                }

                if (kt + 1 < KT) cpa_wait0();
                BARR2;
            }

            int crow = lane >> 2;
            int ccol = (lane & 3) * 2;
            #pragma unroll
            for (int mt = 0; mt < 2; mt++) {
                int r0 = m0 + wm * 32 + mt * 16 + crow;
                #pragma unroll
                for (int nt = 0; nt < 8; nt++) {
                    int cglob = n0 + wn * 64 + nt * 8 + ccol;
                    float b0 = b4[cglob], b1 = b4[cglob + 1];
                    float2 v0 = { acc[mt][nt][0] + b0, acc[mt][nt][1] + b1 };
                    float2 v1 = { acc[mt][nt][2] + b0, acc[mt][nt][3] + b1 };
                    *(float2*)(xz + (size_t)r0 * Ng + cglob)       = v0;
                    *(float2*)(xz + (size_t)(r0 + 8) * Ng + cglob) = v1;
                }
            }

            __threadfence();
            BARR2;
            if (wtid == 0) atomicAdd(ready + (m0 >> 7), 1u);
        }
    }
}

// ---------------------------------------------------------------------------
// In-place row softmax (1024 cols, one block/row).
// ---------------------------------------------------------------------------
__global__ __launch_bounds__(256) void softmax_kernel(float* __restrict__ out) {
    __shared__ float red[8];
    int tid = threadIdx.x;
    float* p = out + (size_t)blockIdx.x * CODES_;

    float4 v = *(float4*)(p + tid * 4);
    float m = fmaxf(fmaxf(v.x, v.y), fmaxf(v.z, v.w));
    #pragma unroll
    for (int o = 16; o > 0; o >>= 1) m = fmaxf(m, __shfl_xor_sync(0xFFFFFFFFu, m, o));
    if ((tid & 31) == 0) red[tid >> 5] = m;
    __syncthreads();
    float bm = red[0];
    #pragma unroll
    for (int i = 1; i < 8; i++) bm = fmaxf(bm, red[i]);
    __syncthreads();

    v.x = expf(v.x - bm); v.y = expf(v.y - bm);
    v.z = expf(v.z - bm); v.w = expf(v.w - bm);
    float s = v.x + v.y + v.z + v.w;
    #pragma unroll
    for (int o = 16; o > 0; o >>= 1) s += __shfl_xor_sync(0xFFFFFFFFu, s, o);
    if ((tid & 31) == 0) red[tid >> 5] = s;
    __syncthreads();
    float bs = red[0];
    #pragma unroll
    for (int i = 1; i < 8; i++) bs += red[i];
    float inv = 1.0f / bs;
    v.x *= inv; v.y *= inv; v.z *= inv; v.w *= inv;
    *(float4*)(p + tid * 4) = v;
}

// ---------------------------------------------------------------------------
// Launch
// ---------------------------------------------------------------------------
extern "C" void kernel_launch(void* const* d_in, const int* in_sizes, int n_in,
                              void* d_out, int out_size) {
    const float* x       = (const float*)d_in[0];
    const float* mask    = (const float*)d_in[1];
    const float* W_in    = (const float*)d_in[2];
    const float* W_rec   = (const float*)d_in[3];
    const float* b_lstm  = (const float*)d_in[4];
    const float* W_dense = (const float*)d_in[5];
    const float* b_dense = (const float*)d_in[6];
    float* out = (float*)d_out;

    float *xz, *hseq, *h0, *Wrec4, *b4;
    unsigned *bar, *q, *ready;
    __nv_bfloat16 *xh, *xl, *Wih, *Wil, *Wdh, *Wdl, *hh, *hl;
    cudaGetSymbolAddress((void**)&xz,    g_xz);
    cudaGetSymbolAddress((void**)&hseq,  g_hseq);
    cudaGetSymbolAddress((void**)&h0,    g_h0);
    cudaGetSymbolAddress((void**)&Wrec4, g_Wrec4);
    cudaGetSymbolAddress((void**)&b4,    g_b4);
    cudaGetSymbolAddress((void**)&bar,   g_bar);
    cudaGetSymbolAddress((void**)&q,     g_q);
    cudaGetSymbolAddress((void**)&ready, g_ready);
    cudaGetSymbolAddress((void**)&xh,    g_xh);
    cudaGetSymbolAddress((void**)&xl,    g_xl);
    cudaGetSymbolAddress((void**)&Wih,   g_Wih);
    cudaGetSymbolAddress((void**)&Wil,   g_Wil);
    cudaGetSymbolAddress((void**)&Wdh,   g_Wdh);
    cudaGetSymbolAddress((void**)&Wdl,   g_Wdl);
    cudaGetSymbolAddress((void**)&hh,    g_hh);
    cudaGetSymbolAddress((void**)&hl,    g_hl);

    cudaFuncSetAttribute(fused_p12,
                         cudaFuncAttributeMaxDynamicSharedMemorySize, FUSED_SMEM);
    cudaFuncSetAttribute(tgemm2,
                         cudaFuncAttributeMaxDynamicSharedMemorySize, GEMM_SMEM);

    // Pre-passes
    reorder_gates<<<(U_ * G4_ + 255) / 256, 256>>>(W_rec, Wrec4, U_ * G4_);
    reorder_split<<<(F_ * G4_ + 255) / 256, 256>>>(W_in, Wih, Wil, F_ * G4_);
    convert_split<<<(U_ * CODES_ / 4 + 255) / 256, 256>>>(W_dense, Wdh, Wdl, U_ * CODES_ / 4);
    convert_split<<<((int)((size_t)ROWS_ * F_ / 4) + 255) / 256, 256>>>(x, xh, xl, (int)((size_t)ROWS_ * F_ / 4));
    init_kernel<<<(B_ * U_ + 255) / 256, 256>>>(b_lstm, b4, h0, bar, q, ready);

    // Phase 1+2 fused
    fused_p12<<<RBLK, 512, FUSED_SMEM>>>(
        xh, xl, Wih, Wil, b4, xz, h0, Wrec4, hseq, bar, q, ready);

    // Phase 2.5: masked h -> bf16 hi/lo
    convert_mask<<<((int)((size_t)ROWS_ * U_ / 4) + 255) / 256, 256>>>(
        hseq, mask, hh, hl, (int)((size_t)ROWS_ * U_ / 4));

    // Phase 3: logits = relu(masked_h @ W_dense + b_dense)
    tgemm2<<<dim3(CODES_ / 128, ROWS_ / 128), 256, GEMM_SMEM>>>(
        hh, hl, Wdh, Wdl, b_dense, out, ROWS_, CODES_, U_, 1);

    // Phase 4: softmax
    softmax_kernel<<<ROWS_, 256>>>(out);
}

// round 17
// speedup vs baseline: 1.5078x; 1.0173x over previous
#include <cuda_runtime.h>
#include <cuda_bf16.h>
#include <math.h>
#include <stdint.h>

// Problem constants
#define T_   256
#define B_   128
#define F_   1024
#define U_   512
#define G4_  2048   // 4*U
#define CODES_ 1024
#define ROWS_ 32768 // T*B

#define RBLK 128    // recurrence blocks (grid barrier population)
#define GRID 148    // total blocks: 128 recurrence+worker, 20 worker-only
#define KC   32     // recurrence K chunk (double-buffered)
#define HP3  36     // Hs row pitch, batch-major [b][kk] (KC+4)

// Tensor GEMM tile: 128x128, K-chunk 64
#define BKT  64
#define APITCH 72
#define BPITCH 136
#define SA_ELEM (128 * APITCH)                  // 9216
#define SB_ELEM (BKT * BPITCH)                  // 8704
#define STAGE_ELEM (2 * SA_ELEM + 2 * SB_ELEM)  // 35840
#define GEMM_SMEM (2 * STAGE_ELEM * 2)          // 143360 B

// Fused kernel smem layout (bytes)
#define FS_WS   GEMM_SMEM                        // 143360: W_rec slice (512x16 f32)
#define FS_HS   (FS_WS + 512 * 16 * 4)           // 176128: Hs double buffer
#define HSBUF_B (B_ * HP3 * 4)                   // 18432 per buffer
#define FS_TILE (FS_HS + 2 * HSBUF_B)            // 212992: tile broadcast slot
#define FUSED_SMEM (FS_TILE + 16)                // 213008

#define P1_TILES (T_ * (G4_ / 128))              // 4096 tiles, 16 per timestep

#define BARR1 asm volatile("bar.sync 1, 256;" ::: "memory")
#define BARR2 asm volatile("bar.sync 2, 256;" ::: "memory")

// ---------------------------------------------------------------------------
// Scratch
// ---------------------------------------------------------------------------
__device__ float g_xz   [(size_t)ROWS_ * G4_];
__device__ float g_hseq [(size_t)ROWS_ * U_];
__device__ float g_h0   [B_ * U_];
__device__ float g_Wrec4[(size_t)U_ * G4_];
__device__ float g_b4   [G4_];
__device__ unsigned g_bar;
__device__ unsigned g_q;
__device__ unsigned g_ready[T_];

__device__ __nv_bfloat16 g_xh [(size_t)ROWS_ * F_];
__device__ __nv_bfloat16 g_xl [(size_t)ROWS_ * F_];
__device__ __nv_bfloat16 g_Wih[(size_t)F_ * G4_];
__device__ __nv_bfloat16 g_Wil[(size_t)F_ * G4_];
__device__ __nv_bfloat16 g_Wdh[(size_t)U_ * CODES_];
__device__ __nv_bfloat16 g_Wdl[(size_t)U_ * CODES_];
__device__ __nv_bfloat16 g_hh [(size_t)ROWS_ * U_];
__device__ __nv_bfloat16 g_hl [(size_t)ROWS_ * U_];

// ---------------------------------------------------------------------------
// Helpers
// ---------------------------------------------------------------------------
__device__ __forceinline__ uint32_t smem_u32(const void* p) {
    return (uint32_t)__cvta_generic_to_shared(p);
}
__device__ __forceinline__ void cpa16(uint32_t dst, const void* src) {
    asm volatile("cp.async.cg.shared.global [%0], [%1], 16;\n" :: "r"(dst), "l"(src));
}
__device__ __forceinline__ void cpa_commit() { asm volatile("cp.async.commit_group;\n" ::); }
__device__ __forceinline__ void cpa_wait0()  { asm volatile("cp.async.wait_group 0;\n" ::); }
__device__ __forceinline__ void ldsm_x4(uint32_t& r0, uint32_t& r1, uint32_t& r2, uint32_t& r3, uint32_t a) {
    asm volatile("ldmatrix.sync.aligned.m8n8.x4.shared.b16 {%0,%1,%2,%3},[%4];"
                 : "=r"(r0), "=r"(r1), "=r"(r2), "=r"(r3) : "r"(a));
}
__device__ __forceinline__ void ldsm_x4t(uint32_t& r0, uint32_t& r1, uint32_t& r2, uint32_t& r3, uint32_t a) {
    asm volatile("ldmatrix.sync.aligned.m8n8.x4.trans.shared.b16 {%0,%1,%2,%3},[%4];"
                 : "=r"(r0), "=r"(r1), "=r"(r2), "=r"(r3) : "r"(a));
}
__device__ __forceinline__ void mma_bf16(float c[4], const uint32_t a[4], const uint32_t b[2]) {
    asm volatile(
        "mma.sync.aligned.m16n8k16.row.col.f32.bf16.bf16.f32 "
        "{%0,%1,%2,%3},{%4,%5,%6,%7},{%8,%9},{%0,%1,%2,%3};"
        : "+f"(c[0]), "+f"(c[1]), "+f"(c[2]), "+f"(c[3])
        : "r"(a[0]), "r"(a[1]), "r"(a[2]), "r"(a[3]), "r"(b[0]), "r"(b[1]));
}

// ---------------------------------------------------------------------------
// Pre-pass kernels
// ---------------------------------------------------------------------------
__global__ void reorder_gates(const float* __restrict__ W, float* __restrict__ W4, int total) {
    int idx = blockIdx.x * blockDim.x + threadIdx.x;
    if (idx >= total) return;
    int col = idx & (G4_ - 1);
    int k   = idx >> 11;
    W4[idx] = W[(size_t)k * G4_ + (col & 3) * U_ + (col >> 2)];
}

__global__ void reorder_split(const float* __restrict__ W,
                              __nv_bfloat16* __restrict__ hi,
                              __nv_bfloat16* __restrict__ lo, int total) {
    int idx = blockIdx.x * blockDim.x + threadIdx.x;
    if (idx >= total) return;
    int col = idx & (G4_ - 1);
    int k   = idx >> 11;
    float v = W[(size_t)k * G4_ + (col & 3) * U_ + (col >> 2)];
    __nv_bfloat16 h = __float2bfloat16(v);
    hi[idx] = h;
    lo[idx] = __float2bfloat16(v - __bfloat162float(h));
}

__global__ void convert_split(const float* __restrict__ src,
                              __nv_bfloat16* __restrict__ hi,
                              __nv_bfloat16* __restrict__ lo, int n4) {
    int idx = blockIdx.x * blockDim.x + threadIdx.x;
    if (idx >= n4) return;
    float4 v = *(const float4*)(src + (size_t)idx * 4);
    __nv_bfloat16 h0 = __float2bfloat16(v.x), h1 = __float2bfloat16(v.y);
    __nv_bfloat16 h2 = __float2bfloat16(v.z), h3 = __float2bfloat16(v.w);
    *(__nv_bfloat162*)(hi + (size_t)idx * 4)     = __halves2bfloat162(h0, h1);
    *(__nv_bfloat162*)(hi + (size_t)idx * 4 + 2) = __halves2bfloat162(h2, h3);
    *(__nv_bfloat162*)(lo + (size_t)idx * 4)     =
        __halves2bfloat162(__float2bfloat16(v.x - __bfloat162float(h0)),
                           __float2bfloat16(v.y - __bfloat162float(h1)));
    *(__nv_bfloat162*)(lo + (size_t)idx * 4 + 2) =
        __halves2bfloat162(__float2bfloat16(v.z - __bfloat162float(h2)),
                           __float2bfloat16(v.w - __bfloat162float(h3)));
}

__global__ void convert_mask(const float* __restrict__ hseq,
                             const float* __restrict__ mask,
                             __nv_bfloat16* __restrict__ hi,
                             __nv_bfloat16* __restrict__ lo, int n4) {
    int idx = blockIdx.x * blockDim.x + threadIdx.x;
    if (idx >= n4) return;
    float m = mask[(idx * 4) >> 9];
    float4 v = *(const float4*)(hseq + (size_t)idx * 4);
    v.x *= m; v.y *= m; v.z *= m; v.w *= m;
    __nv_bfloat16 h0 = __float2bfloat16(v.x), h1 = __float2bfloat16(v.y);
    __nv_bfloat16 h2 = __float2bfloat16(v.z), h3 = __float2bfloat16(v.w);
    *(__nv_bfloat162*)(hi + (size_t)idx * 4)     = __halves2bfloat162(h0, h1);
    *(__nv_bfloat162*)(hi + (size_t)idx * 4 + 2) = __halves2bfloat162(h2, h3);
    *(__nv_bfloat162*)(lo + (size_t)idx * 4)     =
        __halves2bfloat162(__float2bfloat16(v.x - __bfloat162float(h0)),
                           __float2bfloat16(v.y - __bfloat162float(h1)));
    *(__nv_bfloat162*)(lo + (size_t)idx * 4 + 2) =
        __halves2bfloat162(__float2bfloat16(v.z - __bfloat162float(h2)),
                           __float2bfloat16(v.w - __bfloat162float(h3)));
}

__global__ void init_kernel(const float* __restrict__ b_lstm,
                            float* __restrict__ b4,
                            float* __restrict__ h0,
                            unsigned* __restrict__ bar,
                            unsigned* __restrict__ q,
                            unsigned* __restrict__ ready) {
    int idx = blockIdx.x * blockDim.x + threadIdx.x;
    if (idx == 0) { *bar = 0u; *q = 0u; }
    if (idx < T_) ready[idx] = 0u;
    if (idx < G4_) b4[idx] = b_lstm[(idx & 3) * U_ + (idx >> 2)];
    if (idx < B_ * U_) h0[idx] = 0.0f;
}

// ---------------------------------------------------------------------------
// Stand-alone tensor GEMM (BKT=64) for phase 3. (frozen)
// ---------------------------------------------------------------------------
__global__ __launch_bounds__(256, 1) void tgemm2(
    const __nv_bfloat16* __restrict__ Ah, const __nv_bfloat16* __restrict__ Al,
    const __nv_bfloat16* __restrict__ Bh, const __nv_bfloat16* __restrict__ Bl,
    const float* __restrict__ bias, float* __restrict__ C,
    int M, int N, int K, int relu)
{
    extern __shared__ __nv_bfloat16 ts[];

    int tid  = threadIdx.x;
    int warp = tid >> 5, lane = tid & 31;
    int wm = warp >> 1, wn = warp & 1;
    int m0 = blockIdx.y * 128, n0 = blockIdx.x * 128;

    float acc[2][8][4];
    #pragma unroll
    for (int i = 0; i < 2; i++)
        #pragma unroll
        for (int j = 0; j < 8; j++)
            #pragma unroll
            for (int q = 0; q < 4; q++) acc[i][j][q] = 0.0f;

    int a_r = (lane & 15);
    int a_c = (lane >> 4) * 8;
    int aoffA = (wm * 32 + a_r) * APITCH + a_c;
    int aoffB = a_r * BPITCH + wn * 64 + a_c;

    int KT = K / BKT;

    auto load_stage = [&](int kt, int s) {
        __nv_bfloat16* st = ts + s * STAGE_ELEM;
        __nv_bfloat16* sAh = st;
        __nv_bfloat16* sAl = st + SA_ELEM;
        __nv_bfloat16* sBh = st + 2 * SA_ELEM;
        __nv_bfloat16* sBl = st + 2 * SA_ELEM + SB_ELEM;
        int k0 = kt * BKT;
        const __nv_bfloat16* gAh = Ah + (size_t)m0 * K + k0;
        const __nv_bfloat16* gAl = Al + (size_t)m0 * K + k0;
        const __nv_bfloat16* gBh = Bh + (size_t)k0 * N + n0;
        const __nv_bfloat16* gBl = Bl + (size_t)k0 * N + n0;
        #pragma unroll
        for (int j = 0; j < 4; j++) {
            int ca = tid + j * 256;
            int ar = ca >> 3, as = ca & 7;
            cpa16(smem_u32(sAh + ar * APITCH + as * 8), gAh + (size_t)ar * K + as * 8);
            cpa16(smem_u32(sAl + ar * APITCH + as * 8), gAl + (size_t)ar * K + as * 8);
            int br = ca >> 4, bs = ca & 15;
            cpa16(smem_u32(sBh + br * BPITCH + bs * 8), gBh + (size_t)br * N + bs * 8);
            cpa16(smem_u32(sBl + br * BPITCH + bs * 8), gBl + (size_t)br * N + bs * 8);
        }
    };

    load_stage(0, 0);
    cpa_commit();
    cpa_wait0();
    __syncthreads();

    for (int kt = 0; kt < KT; kt++) {
        int cur = kt & 1;
        if (kt + 1 < KT) {
            load_stage(kt + 1, cur ^ 1);
            cpa_commit();
        }

        __nv_bfloat16* st = ts + cur * STAGE_ELEM;
        uint32_t aAh = smem_u32(st + aoffA);
        uint32_t aAl = smem_u32(st + SA_ELEM + aoffA);
        uint32_t aBh = smem_u32(st + 2 * SA_ELEM + aoffB);
        uint32_t aBl = smem_u32(st + 2 * SA_ELEM + SB_ELEM + aoffB);

        #pragma unroll
        for (int kk = 0; kk < 4; kk++) {
            uint32_t Ahf[2][4], Alf[2][4];
            #pragma unroll
            for (int mt = 0; mt < 2; mt++) {
                uint32_t off = (mt * 16) * APITCH * 2 + kk * 16 * 2;
                ldsm_x4(Ahf[mt][0], Ahf[mt][1], Ahf[mt][2], Ahf[mt][3], aAh + off);
                ldsm_x4(Alf[mt][0], Alf[mt][1], Alf[mt][2], Alf[mt][3], aAl + off);
            }
            uint32_t Bhf[8][2], Blf[8][2];
            #pragma unroll
            for (int p = 0; p < 4; p++) {
                uint32_t off = (kk * 16) * BPITCH * 2 + p * 16 * 2;
                ldsm_x4t(Bhf[2*p][0], Bhf[2*p][1], Bhf[2*p+1][0], Bhf[2*p+1][1], aBh + off);
                ldsm_x4t(Blf[2*p][0], Blf[2*p][1], Blf[2*p+1][0], Blf[2*p+1][1], aBl + off);
            }
            #pragma unroll
            for (int mt = 0; mt < 2; mt++)
                #pragma unroll
                for (int nt = 0; nt < 8; nt++) {
                    mma_bf16(acc[mt][nt], Ahf[mt], Bhf[nt]);
                    mma_bf16(acc[mt][nt], Ahf[mt], Blf[nt]);
                    mma_bf16(acc[mt][nt], Alf[mt], Bhf[nt]);
                }
        }

        if (kt + 1 < KT) cpa_wait0();
        __syncthreads();
    }

    int crow = lane >> 2;
    int ccol = (lane & 3) * 2;
    #pragma unroll
    for (int mt = 0; mt < 2; mt++) {
        int r0 = m0 + wm * 32 + mt * 16 + crow;
        #pragma unroll
        for (int nt = 0; nt < 8; nt++) {
            int cglob = n0 + wn * 64 + nt * 8 + ccol;
            float b0 = bias[cglob], b1 = bias[cglob + 1];
            float2 v0 = { acc[mt][nt][0] + b0, acc[mt][nt][1] + b1 };
            float2 v1 = { acc[mt][nt][2] + b0, acc[mt][nt][3] + b1 };
            if (relu) {
                v0.x = fmaxf(v0.x, 0.f); v0.y = fmaxf(v0.y, 0.f);
                v1.x = fmaxf(v1.x, 0.f); v1.y = fmaxf(v1.y, 0.f);
            }
            *(float2*)(C + (size_t)r0 * N + cglob)       = v0;
            *(float2*)(C + (size_t)(r0 + 8) * N + cglob) = v1;
        }
    }
}

// ---------------------------------------------------------------------------
// FUSED phase1+phase2 (R16 structure). Grid 148:
//   blocks [0,128): tid<256 recurrence (R16 verbatim), tid>=256 GEMM worker
//   blocks [128,148): tid<256 exit, tid>=256 GEMM worker (extra capacity on
//                     the 20 otherwise-idle SMs)
// Grid barrier population stays 128 (only recurrence blocks arrive).
// ---------------------------------------------------------------------------
__global__ __launch_bounds__(512, 1) void fused_p12(
    const __nv_bfloat16* __restrict__ Ah, const __nv_bfloat16* __restrict__ Al,
    const __nv_bfloat16* __restrict__ Bh, const __nv_bfloat16* __restrict__ Bl,
    const float* __restrict__ b4, float* xz,
    const float* __restrict__ h0, const float* __restrict__ Wrec,
    float* hseq, unsigned* bar, unsigned* q, unsigned* ready)
{
    extern __shared__ char smemc[];
    int tid = threadIdx.x;

    if (tid < 256) {
        if (blockIdx.x >= RBLK) return;          // worker-only block: idle half
        // ------------------ RECURRENCE ROLE (bar 1) -----------------------
        float* Ws  = (float*)(smemc + FS_WS);    // [512][16]
        float* Hs0 = (float*)(smemc + FS_HS);    // [B_][HP3]
        float* Hs1 = (float*)(smemc + FS_HS + HSBUF_B);
        int rtid = tid;
        int blk = blockIdx.x;
        int n0 = blk * 16;
        int tx = rtid & 3;
        int ty = rtid >> 2;                      // 0..63; batches ty, ty+64
        int u  = blk * 4 + tx;

        for (int l = rtid; l < 512 * 4; l += 256) {
            int row = l >> 2, c4 = l & 3;
            *(float4*)&Ws[row * 16 + c4 * 4] =
                *(const float4*)(Wrec + (size_t)row * G4_ + n0 + c4 * 4);
        }

        float creg0 = 0.0f, creg1 = 0.0f;
        const float* hp = h0;

        for (int t = 0; t < T_; t++) {
            float acc[2][4];
            #pragma unroll
            for (int i = 0; i < 2; i++)
                #pragma unroll
                for (int j = 0; j < 4; j++) acc[i][j] = 0.0f;

            // prologue: stage chunk 0 into Hs0
            #pragma unroll
            for (int i = 0; i < 4; i++) {
                int l = rtid + i * 256;
                int b = l >> 3, k4 = l & 7;
                cpa16(smem_u32(Hs0 + b * HP3 + k4 * 4),
                      hp + (size_t)b * U_ + k4 * 4);
            }
            cpa_commit();
            cpa_wait0();
            BARR1;

            #pragma unroll
            for (int c = 0; c < 16; c++) {
                float* cur = (c & 1) ? Hs1 : Hs0;
                float* nxt = (c & 1) ? Hs0 : Hs1;
                if (c < 15) {                    // stage chunk c+1 (async)
                    int k0n = (c + 1) * KC;
                    #pragma unroll
                    for (int i = 0; i < 4; i++) {
                        int l = rtid + i * 256;
                        int b = l >> 3, k4 = l & 7;
                        cpa16(smem_u32(nxt + b * HP3 + k4 * 4),
                              hp + (size_t)b * U_ + k0n + k4 * 4);
                    }
                    cpa_commit();
                }

                int k0 = c * KC;
                #pragma unroll
                for (int kk = 0; kk < KC; kk++) {
                    float4 wv = *(float4*)&Ws[(k0 + kk) * 16 + tx * 4];
                    float ha = cur[ty * HP3 + kk];
                    float hb = cur[(ty + 64) * HP3 + kk];
                    acc[0][0] += ha * wv.x; acc[0][1] += ha * wv.y;
                    acc[0][2] += ha * wv.z; acc[0][3] += ha * wv.w;
                    acc[1][0] += hb * wv.x; acc[1][1] += hb * wv.y;
                    acc[1][2] += hb * wv.z; acc[1][3] += hb * wv.w;
                }

                if (c < 15) cpa_wait0();
                BARR1;
            }

            if (rtid == 0) {
                while (((volatile unsigned*)ready)[t] < 16u) {}
                __threadfence();
            }
            BARR1;

            #pragma unroll
            for (int i = 0; i < 2; i++) {
                int b = ty + 64 * i;
                const float4* xzp = (const float4*)(xz + ((size_t)t * B_ + b) * G4_ + n0 + tx * 4);
                float4 xv = __ldcg(xzp);
                float zi = acc[i][0] + xv.x;
                float zf = acc[i][1] + xv.y;
                float zg = acc[i][2] + xv.z;
                float zo = acc[i][3] + xv.w;
                float ig = 1.0f / (1.0f + expf(-zi));
                float fg = 1.0f / (1.0f + expf(-zf));
                float gg = tanhf(zg);
                float og = 1.0f / (1.0f + expf(-zo));
                float cp = i ? creg1 : creg0;
                float cn = fg * cp + ig * gg;
                if (i) creg1 = cn; else creg0 = cn;
                hseq[((size_t)t * B_ + b) * U_ + u] = og * tanhf(cn);
            }

            __threadfence();
            BARR1;
            if (rtid == 0) {
                atomicAdd(bar, 1u);
                unsigned target = (unsigned)RBLK * (unsigned)(t + 1);
                while (*(volatile unsigned*)bar < target) {}
            }
            BARR1;

            hp = hseq + (size_t)t * B_ * U_;
        }
    } else {
        // ------------------ GEMM ROLE (phase 1, BKT=64, bar 2) ------------
        __nv_bfloat16* ts = (__nv_bfloat16*)smemc;
        volatile int* sm_tile = (volatile int*)(smemc + FS_TILE);
        int wtid = tid - 256;
        int warp = wtid >> 5, lane = wtid & 31;
        int wm = warp >> 1, wn = warp & 1;

        int a_r = (lane & 15);
        int a_c = (lane >> 4) * 8;
        int aoffA = (wm * 32 + a_r) * APITCH + a_c;
        int aoffB = a_r * BPITCH + wn * 64 + a_c;

        const int Kg = F_, Ng = G4_, KT = F_ / BKT;

        for (;;) {
            if (wtid == 0) *sm_tile = (int)atomicAdd(q, 1u);
            BARR2;
            int tile = *sm_tile;
            BARR2;
            if (tile >= P1_TILES) break;
            int m0 = (tile >> 4) * 128;     // t-major: tile = t*16 + ncol
            int n0 = (tile & 15) * 128;

            float acc[2][8][4];
            #pragma unroll
            for (int i = 0; i < 2; i++)
                #pragma unroll
                for (int j = 0; j < 8; j++)
                    #pragma unroll
                    for (int qq = 0; qq < 4; qq++) acc[i][j][qq] = 0.0f;

            auto load_stage = [&](int kt, int s) {
                __nv_bfloat16* st = ts + s * STAGE_ELEM;
                __nv_bfloat16* sAh = st;
                __nv_bfloat16* sAl = st + SA_ELEM;
                __nv_bfloat16* sBh = st + 2 * SA_ELEM;
                __nv_bfloat16* sBl = st + 2 * SA_ELEM + SB_ELEM;
                int k0 = kt * BKT;
                const __nv_bfloat16* gAh = Ah + (size_t)m0 * Kg + k0;
                const __nv_bfloat16* gAl = Al + (size_t)m0 * Kg + k0;
                const __nv_bfloat16* gBh = Bh + (size_t)k0 * Ng + n0;
                const __nv_bfloat16* gBl = Bl + (size_t)k0 * Ng + n0;
                #pragma unroll
                for (int j = 0; j < 4; j++) {
                    int ca = wtid + j * 256;
                    int ar = ca >> 3, as = ca & 7;
                    cpa16(smem_u32(sAh + ar * APITCH + as * 8), gAh + (size_t)ar * Kg + as * 8);
                    cpa16(smem_u32(sAl + ar * APITCH + as * 8), gAl + (size_t)ar * Kg + as * 8);
                    int br = ca >> 4, bs = ca & 15;
                    cpa16(smem_u32(sBh + br * BPITCH + bs * 8), gBh + (size_t)br * Ng + bs * 8);
                    cpa16(smem_u32(sBl + br * BPITCH + bs * 8), gBl + (size_t)br * Ng + bs * 8);
                }
            };

            load_stage(0, 0);
            cpa_commit();
            cpa_wait0();
            BARR2;

            for (int kt = 0; kt < KT; kt++) {
                int cur = kt & 1;
                if (kt + 1 < KT) {
                    load_stage(kt + 1, cur ^ 1);
                    cpa_commit();
                }

                __nv_bfloat16* st = ts + cur * STAGE_ELEM;
                uint32_t aAh = smem_u32(st + aoffA);
                uint32_t aAl = smem_u32(st + SA_ELEM + aoffA);
                uint32_t aBh = smem_u32(st + 2 * SA_ELEM + aoffB);
                uint32_t aBl = smem_u32(st + 2 * SA_ELEM + SB_ELEM + aoffB);

                #pragma unroll
                for (int kk = 0; kk < 4; kk++) {
                    uint32_t Ahf[2][4], Alf[2][4];
                    #pragma unroll
                    for (int mt = 0; mt < 2; mt++) {
                        uint32_t off = (mt * 16) * APITCH * 2 + kk * 16 * 2;
                        ldsm_x4(Ahf[mt][0], Ahf[mt][1], Ahf[mt][2], Ahf[mt][3], aAh + off);
                        ldsm_x4(Alf[mt][0], Alf[mt][1], Alf[mt][2], Alf[mt][3], aAl + off);
                    }
                    uint32_t Bhf[8][2], Blf[8][2];
                    #pragma unroll
                    for (int p = 0; p < 4; p++) {
                        uint32_t off = (kk * 16) * BPITCH * 2 + p * 16 * 2;
                        ldsm_x4t(Bhf[2*p][0], Bhf[2*p][1], Bhf[2*p+1][0], Bhf[2*p+1][1], aBh + off);
                        ldsm_x4t(Blf[2*p][0], Blf[2*p][1], Blf[2*p+1][0], Blf[2*p+1][1], aBl + off);
                    }
                    #pragma unroll
                    for (int mt = 0; mt < 2; mt++)
                        #pragma unroll
                        for (int nt = 0; nt < 8; nt++) {
                            mma_bf16(acc[mt][nt], Ahf[mt], Bhf[nt]);
                            mma_bf16(acc[mt][nt], Ahf[mt], Blf[nt]);
                            mma_bf16(acc[mt][nt], Alf[mt], Bhf[nt]);
                        }
                }

                if (kt + 1 < KT) cpa_wait0();
                BARR2;
            }

            int crow = lane >> 2;
            int ccol = (lane & 3) * 2;
            #pragma unroll
            for (int mt = 0; mt < 2; mt++) {
                int r0 = m0 + wm * 32 + mt * 16 + crow;
                #pragma unroll
                for (int nt = 0; nt < 8; nt++) {
                    int cglob = n0 + wn * 64 + nt * 8 + ccol;
                    float b0 = b4[cglob], b1 = b4[cglob + 1];
                    float2 v0 = { acc[mt][nt][0] + b0, acc[mt][nt][1] + b1 };
                    float2 v1 = { acc[mt][nt][2] + b0, acc[mt][nt][3] + b1 };
                    *(float2*)(xz + (size_t)r0 * Ng + cglob)       = v0;
                    *(float2*)(xz + (size_t)(r0 + 8) * Ng + cglob) = v1;
                }
            }

            __threadfence();
            BARR2;
            if (wtid == 0) atomicAdd(ready + (m0 >> 7), 1u);
        }
    }
}

// ---------------------------------------------------------------------------
// In-place row softmax (1024 cols, one block/row).
// ---------------------------------------------------------------------------
__global__ __launch_bounds__(256) void softmax_kernel(float* __restrict__ out) {
    __shared__ float red[8];
    int tid = threadIdx.x;
    float* p = out + (size_t)blockIdx.x * CODES_;

    float4 v = *(float4*)(p + tid * 4);
    float m = fmaxf(fmaxf(v.x, v.y), fmaxf(v.z, v.w));
    #pragma unroll
    for (int o = 16; o > 0; o >>= 1) m = fmaxf(m, __shfl_xor_sync(0xFFFFFFFFu, m, o));
    if ((tid & 31) == 0) red[tid >> 5] = m;
    __syncthreads();
    float bm = red[0];
    #pragma unroll
    for (int i = 1; i < 8; i++) bm = fmaxf(bm, red[i]);
    __syncthreads();

    v.x = expf(v.x - bm); v.y = expf(v.y - bm);
    v.z = expf(v.z - bm); v.w = expf(v.w - bm);
    float s = v.x + v.y + v.z + v.w;
    #pragma unroll
    for (int o = 16; o > 0; o >>= 1) s += __shfl_xor_sync(0xFFFFFFFFu, s, o);
    if ((tid & 31) == 0) red[tid >> 5] = s;
    __syncthreads();
    float bs = red[0];
    #pragma unroll
    for (int i = 1; i < 8; i++) bs += red[i];
    float inv = 1.0f / bs;
    v.x *= inv; v.y *= inv; v.z *= inv; v.w *= inv;
    *(float4*)(p + tid * 4) = v;
}

// ---------------------------------------------------------------------------
// Launch
// ---------------------------------------------------------------------------
extern "C" void kernel_launch(void* const* d_in, const int* in_sizes, int n_in,
                              void* d_out, int out_size) {
    const float* x       = (const float*)d_in[0];
    const float* mask    = (const float*)d_in[1];
    const float* W_in    = (const float*)d_in[2];
    const float* W_rec   = (const float*)d_in[3];
    const float* b_lstm  = (const float*)d_in[4];
    const float* W_dense = (const float*)d_in[5];
    const float* b_dense = (const float*)d_in[6];
    float* out = (float*)d_out;

    float *xz, *hseq, *h0, *Wrec4, *b4;
    unsigned *bar, *q, *ready;
    __nv_bfloat16 *xh, *xl, *Wih, *Wil, *Wdh, *Wdl, *hh, *hl;
    cudaGetSymbolAddress((void**)&xz,    g_xz);
    cudaGetSymbolAddress((void**)&hseq,  g_hseq);
    cudaGetSymbolAddress((void**)&h0,    g_h0);
    cudaGetSymbolAddress((void**)&Wrec4, g_Wrec4);
    cudaGetSymbolAddress((void**)&b4,    g_b4);
    cudaGetSymbolAddress((void**)&bar,   g_bar);
    cudaGetSymbolAddress((void**)&q,     g_q);
    cudaGetSymbolAddress((void**)&ready, g_ready);
    cudaGetSymbolAddress((void**)&xh,    g_xh);
    cudaGetSymbolAddress((void**)&xl,    g_xl);
    cudaGetSymbolAddress((void**)&Wih,   g_Wih);
    cudaGetSymbolAddress((void**)&Wil,   g_Wil);
    cudaGetSymbolAddress((void**)&Wdh,   g_Wdh);
    cudaGetSymbolAddress((void**)&Wdl,   g_Wdl);
    cudaGetSymbolAddress((void**)&hh,    g_hh);
    cudaGetSymbolAddress((void**)&hl,    g_hl);

    cudaFuncSetAttribute(fused_p12,
                         cudaFuncAttributeMaxDynamicSharedMemorySize, FUSED_SMEM);
    cudaFuncSetAttribute(tgemm2,
                         cudaFuncAttributeMaxDynamicSharedMemorySize, GEMM_SMEM);

    // Pre-passes
    reorder_gates<<<(U_ * G4_ + 255) / 256, 256>>>(W_rec, Wrec4, U_ * G4_);
    reorder_split<<<(F_ * G4_ + 255) / 256, 256>>>(W_in, Wih, Wil, F_ * G4_);
    convert_split<<<(U_ * CODES_ / 4 + 255) / 256, 256>>>(W_dense, Wdh, Wdl, U_ * CODES_ / 4);
    convert_split<<<((int)((size_t)ROWS_ * F_ / 4) + 255) / 256, 256>>>(x, xh, xl, (int)((size_t)ROWS_ * F_ / 4));
    init_kernel<<<(B_ * U_ + 255) / 256, 256>>>(b_lstm, b4, h0, bar, q, ready);

    // Phase 1+2 fused (148 blocks: 128 recurrence+worker, 20 worker-only)
    fused_p12<<<GRID, 512, FUSED_SMEM>>>(
        xh, xl, Wih, Wil, b4, xz, h0, Wrec4, hseq, bar, q, ready);

    // Phase 2.5: masked h -> bf16 hi/lo
    convert_mask<<<((int)((size_t)ROWS_ * U_ / 4) + 255) / 256, 256>>>(
        hseq, mask, hh, hl, (int)((size_t)ROWS_ * U_ / 4));

    // Phase 3: logits = relu(masked_h @ W_dense + b_dense)
    tgemm2<<<dim3(CODES_ / 128, ROWS_ / 128), 256, GEMM_SMEM>>>(
        hh, hl, Wdh, Wdl, b_dense, out, ROWS_, CODES_, U_, 1);

    // Phase 4: softmax
    softmax_kernel<<<ROWS_, 256>>>(out);
}